// round 2
// baseline (speedup 1.0000x reference)
#include <cuda_runtime.h>

#define N_NODES 20000
#define EDGES   640000
#define C       256   // C_IN == C_OUT

// ---------------- scratch (no allocations allowed) ----------------
__device__ float g_bufA[N_NODES * C];   // normalized x / hop ping
__device__ float g_bufB[N_NODES * C];   // hop pong
__device__ float g_deg[N_NODES];        // deg, then deg^-1/2 in place
__device__ float g_norm[EDGES];         // per-edge GCN norm
__device__ int   g_row[EDGES];          // materialized int32 indices
__device__ int   g_col[EDGES];
__device__ int   g_idx64;               // 1 if edge_index is int64

// ---------------- kernels ----------------

__global__ void zero_kernel(float* __restrict__ p, int n) {
    int i = blockIdx.x * blockDim.x + threadIdx.x;
    int stride = gridDim.x * blockDim.x;
    for (; i < n; i += stride) p[i] = 0.0f;
}

// Decide whether the edge_index buffer holds int64 or int32.
// int64 view of valid int64 data: all values in [0, N_NODES).
// int64 view of int32 data: high word = neighboring index, ~never all zero.
__global__ void detect_kernel(const void* ei) {
    __shared__ int bad;
    if (threadIdx.x == 0) bad = 0;
    __syncthreads();
    const long long* p = (const long long*)ei;
    for (int i = threadIdx.x; i < 2048; i += blockDim.x) {
        long long v = p[i];
        if (v < 0 || v >= N_NODES) bad = 1;
    }
    __syncthreads();
    if (threadIdx.x == 0) g_idx64 = bad ? 0 : 1;
}

// Materialize int32 row/col (dtype-agnostic downstream) + weighted in-degree.
__global__ void extract_deg_kernel(const void* ei, const float* __restrict__ w) {
    int e = blockIdx.x * blockDim.x + threadIdx.x;
    if (e >= EDGES) return;
    int is64 = g_idx64;
    long long r, c;
    if (is64) {
        r = ((const long long*)ei)[e];
        c = ((const long long*)ei)[EDGES + e];
    } else {
        r = ((const int*)ei)[e];
        c = ((const int*)ei)[EDGES + e];
    }
    // defensive clamp: never crash, surface errors as rel_err instead
    if (r < 0 || r >= N_NODES) r = 0;
    if (c < 0 || c >= N_NODES) c = 0;
    g_row[e] = (int)r;
    g_col[e] = (int)c;
    atomicAdd(&g_deg[c], w[e]);
}

// deg -> deg^{-1/2} (0 where deg<=0), in place
__global__ void dis_kernel() {
    int i = blockIdx.x * blockDim.x + threadIdx.x;
    if (i >= N_NODES) return;
    float d = g_deg[i];
    g_deg[i] = (d > 0.0f) ? rsqrtf(d) : 0.0f;
}

// norm[e] = dis[row] * w[e] * dis[col]
__global__ void norm_kernel(const float* __restrict__ w) {
    int e = blockIdx.x * blockDim.x + threadIdx.x;
    if (e >= EDGES) return;
    g_norm[e] = g_deg[g_row[e]] * w[e] * g_deg[g_col[e]];
}

// one warp per row: L2-normalize x -> g_bufA
__global__ void normalize_kernel(const float* __restrict__ x) {
    int warp = (blockIdx.x * blockDim.x + threadIdx.x) >> 5;
    int lane = threadIdx.x & 31;
    if (warp >= N_NODES) return;
    const float4* xr = reinterpret_cast<const float4*>(x + (size_t)warp * C);
    float4 v0 = xr[lane];
    float4 v1 = xr[lane + 32];
    float ss = v0.x*v0.x + v0.y*v0.y + v0.z*v0.z + v0.w*v0.w
             + v1.x*v1.x + v1.y*v1.y + v1.z*v1.z + v1.w*v1.w;
    #pragma unroll
    for (int o = 16; o; o >>= 1) ss += __shfl_xor_sync(0xffffffffu, ss, o);
    float inv = 1.0f / fmaxf(sqrtf(ss), 1e-12f);
    float4* yr = reinterpret_cast<float4*>(g_bufA + (size_t)warp * C);
    v0.x *= inv; v0.y *= inv; v0.z *= inv; v0.w *= inv;
    v1.x *= inv; v1.y *= inv; v1.z *= inv; v1.w *= inv;
    yr[lane]      = v0;
    yr[lane + 32] = v1;
}

// one warp per edge: dst[col,:] += norm * src[row,:]
__global__ void scatter_kernel(const float* __restrict__ src,
                               float* __restrict__ dst) {
    int e = (blockIdx.x * blockDim.x + threadIdx.x) >> 5;
    int lane = threadIdx.x & 31;
    if (e >= EDGES) return;
    int r = g_row[e];
    int c = g_col[e];
    float nv = g_norm[e];
    const float4* s = reinterpret_cast<const float4*>(src + (size_t)r * C);
    float* d = dst + (size_t)c * C;
    #pragma unroll
    for (int k = 0; k < 2; k++) {
        float4 v = s[lane + k * 32];
        int col = (lane + k * 32) * 4;
        atomicAdd(d + col + 0, nv * v.x);
        atomicAdd(d + col + 1, nv * v.y);
        atomicAdd(d + col + 2, nv * v.z);
        atomicAdd(d + col + 3, nv * v.w);
    }
}

// out[M,256] = A[M,256] @ W[256,256]^T + bias
// 64x64 tile, BK=16, 256 threads, each 4x4 micro-tile
__global__ void gemm_kernel(const float* __restrict__ A,
                            const float* __restrict__ W,
                            const float* __restrict__ bias,
                            float* __restrict__ out) {
    __shared__ float As[16][65];  // As[k][m]
    __shared__ float Bs[16][65];  // Bs[k][n] = W[n][k]
    int tid = threadIdx.x;
    int tx = tid & 15;       // output col group
    int ty = tid >> 4;       // output row group
    int m0 = blockIdx.x * 64;
    int n0 = blockIdx.y * 64;

    int lm = tid >> 2;         // 0..63
    int lk = (tid & 3) * 4;    // 0,4,8,12

    float acc[4][4] = {};

    for (int k0 = 0; k0 < C; k0 += 16) {
        int am = m0 + lm;
        float4 av = make_float4(0.f, 0.f, 0.f, 0.f);
        if (am < N_NODES)
            av = *reinterpret_cast<const float4*>(A + (size_t)am * C + k0 + lk);
        As[lk + 0][lm] = av.x;
        As[lk + 1][lm] = av.y;
        As[lk + 2][lm] = av.z;
        As[lk + 3][lm] = av.w;

        float4 bv = *reinterpret_cast<const float4*>(W + (size_t)(n0 + lm) * C + k0 + lk);
        Bs[lk + 0][lm] = bv.x;
        Bs[lk + 1][lm] = bv.y;
        Bs[lk + 2][lm] = bv.z;
        Bs[lk + 3][lm] = bv.w;
        __syncthreads();

        #pragma unroll
        for (int kk = 0; kk < 16; kk++) {
            float a[4], b[4];
            #pragma unroll
            for (int i = 0; i < 4; i++) a[i] = As[kk][ty * 4 + i];
            #pragma unroll
            for (int j = 0; j < 4; j++) b[j] = Bs[kk][tx * 4 + j];
            #pragma unroll
            for (int i = 0; i < 4; i++)
                #pragma unroll
                for (int j = 0; j < 4; j++)
                    acc[i][j] += a[i] * b[j];
        }
        __syncthreads();
    }

    #pragma unroll
    for (int i = 0; i < 4; i++) {
        int m = m0 + ty * 4 + i;
        if (m >= N_NODES) continue;
        #pragma unroll
        for (int j = 0; j < 4; j++) {
            int n = n0 + tx * 4 + j;
            out[(size_t)m * C + n] = acc[i][j] + bias[n];
        }
    }
}

// ---------------- launch ----------------

extern "C" void kernel_launch(void* const* d_in, const int* in_sizes, int n_in,
                              void* d_out, int out_size) {
    const float* x  = (const float*)d_in[0];
    const void*  ei = d_in[1];
    const float* w  = (const float*)d_in[2];
    const float* lw = (const float*)d_in[3];
    const float* lb = (const float*)d_in[4];
    float* out = (float*)d_out;

    float *bufA, *bufB, *deg;
    cudaGetSymbolAddress((void**)&bufA, g_bufA);
    cudaGetSymbolAddress((void**)&bufB, g_bufB);
    cudaGetSymbolAddress((void**)&deg,  g_deg);

    const int T = 256;

    // 0) dtype detection + index materialization + degree
    detect_kernel<<<1, 256>>>(ei);
    zero_kernel<<<160, T>>>(deg, N_NODES);
    extract_deg_kernel<<<(EDGES + T - 1) / T, T>>>(ei, w);
    dis_kernel<<<(N_NODES + T - 1) / T, T>>>();
    norm_kernel<<<(EDGES + T - 1) / T, T>>>(w);

    // 1) normalize rows -> bufA
    normalize_kernel<<<(N_NODES * 32 + T - 1) / T, T>>>(x);

    // 2) hop 1: bufA -> bufB
    zero_kernel<<<2048, T>>>(bufB, N_NODES * C);
    scatter_kernel<<<(EDGES * 32 + T - 1) / T, T>>>(bufA, bufB);

    // 3) hop 2: bufB -> bufA
    zero_kernel<<<2048, T>>>(bufA, N_NODES * C);
    scatter_kernel<<<(EDGES * 32 + T - 1) / T, T>>>(bufB, bufA);

    // 4) linear: out = bufA @ W^T + b
    dim3 ggrid((N_NODES + 63) / 64, C / 64);
    gemm_kernel<<<ggrid, T>>>(bufA, lw, lb, out);
}

// round 3
// speedup vs baseline: 3.4490x; 3.4490x over previous
#include <cuda_runtime.h>

#define N_NODES 20000
#define EDGES   640000
#define C       256

// ---------------- scratch ----------------
__device__ float g_bufA[N_NODES * C];
__device__ float g_bufB[N_NODES * C];
__device__ float g_deg[N_NODES];        // weighted deg -> deg^-1/2
__device__ int   g_cnt[N_NODES];        // in-degree count
__device__ int   g_ptr[N_NODES + 1];    // CSR row pointers (by target)
__device__ int   g_cursor[N_NODES];     // fill cursors
__device__ int   g_srcidx[EDGES];       // CSR: source node per slot
__device__ float g_wval[EDGES];         // CSR: gcn-norm weight per slot
__device__ int   g_row[EDGES];
__device__ int   g_col[EDGES];
__device__ int   g_idx64;

// ---------------- setup kernels ----------------

__global__ void zero_f(float* __restrict__ p, int n) {
    int i = blockIdx.x * blockDim.x + threadIdx.x;
    for (int s = gridDim.x * blockDim.x; i < n; i += s) p[i] = 0.0f;
}
__global__ void zero_i(int* __restrict__ p, int n) {
    int i = blockIdx.x * blockDim.x + threadIdx.x;
    for (int s = gridDim.x * blockDim.x; i < n; i += s) p[i] = 0;
}

// int64 vs int32 edge_index detection (device-side, graph-safe)
__global__ void detect_kernel(const void* ei) {
    __shared__ int bad;
    if (threadIdx.x == 0) bad = 0;
    __syncthreads();
    const long long* p = (const long long*)ei;
    for (int i = threadIdx.x; i < 2048; i += blockDim.x) {
        long long v = p[i];
        if (v < 0 || v >= N_NODES) bad = 1;
    }
    __syncthreads();
    if (threadIdx.x == 0) g_idx64 = bad ? 0 : 1;
}

// materialize int32 indices, weighted degree, integer in-degree histogram
__global__ void extract_kernel(const void* ei, const float* __restrict__ w) {
    int e = blockIdx.x * blockDim.x + threadIdx.x;
    if (e >= EDGES) return;
    long long r, c;
    if (g_idx64) {
        r = ((const long long*)ei)[e];
        c = ((const long long*)ei)[EDGES + e];
    } else {
        r = ((const int*)ei)[e];
        c = ((const int*)ei)[EDGES + e];
    }
    if (r < 0 || r >= N_NODES) r = 0;
    if (c < 0 || c >= N_NODES) c = 0;
    g_row[e] = (int)r;
    g_col[e] = (int)c;
    atomicAdd(&g_deg[c], w[e]);
    atomicAdd(&g_cnt[c], 1);
}

__global__ void dis_kernel() {
    int i = blockIdx.x * blockDim.x + threadIdx.x;
    if (i >= N_NODES) return;
    float d = g_deg[i];
    g_deg[i] = (d > 0.0f) ? rsqrtf(d) : 0.0f;
}

// single-block exclusive prefix sum over g_cnt -> g_ptr (+ cursor copy)
__global__ void scan_kernel() {
    __shared__ int wsum[32];
    __shared__ int s_running;
    int tid = threadIdx.x;            // 1024 threads
    int lane = tid & 31, wid = tid >> 5;
    if (tid == 0) s_running = 0;
    __syncthreads();
    for (int base = 0; base < N_NODES; base += 1024) {
        int i = base + tid;
        int v = (i < N_NODES) ? g_cnt[i] : 0;
        int s = v;
        #pragma unroll
        for (int o = 1; o < 32; o <<= 1) {
            int t = __shfl_up_sync(0xffffffffu, s, o);
            if (lane >= o) s += t;
        }
        if (lane == 31) wsum[wid] = s;
        __syncthreads();
        if (wid == 0) {
            int ws = wsum[lane];
            #pragma unroll
            for (int o = 1; o < 32; o <<= 1) {
                int t = __shfl_up_sync(0xffffffffu, ws, o);
                if (lane >= o) ws += t;
            }
            wsum[lane] = ws;
        }
        __syncthreads();
        int excl = s_running + s - v + (wid > 0 ? wsum[wid - 1] : 0);
        if (i < N_NODES) {
            g_ptr[i] = excl;
            g_cursor[i] = excl;
        }
        __syncthreads();
        if (tid == 0) s_running += wsum[31];
        __syncthreads();
    }
    if (tid == 0) g_ptr[N_NODES] = s_running;
}

// fill CSR: slot per edge under its target node, weight = gcn norm
__global__ void fill_kernel(const float* __restrict__ w) {
    int e = blockIdx.x * blockDim.x + threadIdx.x;
    if (e >= EDGES) return;
    int r = g_row[e], c = g_col[e];
    int pos = atomicAdd(&g_cursor[c], 1);
    g_srcidx[pos] = r;
    g_wval[pos]  = g_deg[r] * w[e] * g_deg[c];
}

// warp per row: L2-normalize x -> g_bufA
__global__ void normalize_kernel(const float* __restrict__ x) {
    int warp = (blockIdx.x * blockDim.x + threadIdx.x) >> 5;
    int lane = threadIdx.x & 31;
    if (warp >= N_NODES) return;
    const float4* xr = reinterpret_cast<const float4*>(x + (size_t)warp * C);
    float4 v0 = xr[lane];
    float4 v1 = xr[lane + 32];
    float ss = v0.x*v0.x + v0.y*v0.y + v0.z*v0.z + v0.w*v0.w
             + v1.x*v1.x + v1.y*v1.y + v1.z*v1.z + v1.w*v1.w;
    #pragma unroll
    for (int o = 16; o; o >>= 1) ss += __shfl_xor_sync(0xffffffffu, ss, o);
    float inv = 1.0f / fmaxf(sqrtf(ss), 1e-12f);
    float4* yr = reinterpret_cast<float4*>(g_bufA + (size_t)warp * C);
    v0.x *= inv; v0.y *= inv; v0.z *= inv; v0.w *= inv;
    v1.x *= inv; v1.y *= inv; v1.z *= inv; v1.w *= inv;
    yr[lane]      = v0;
    yr[lane + 32] = v1;
}

// warp per target node: dst[n,:] = sum_i w[i] * src[srcidx[i],:]  (no atomics)
__global__ void gather_kernel(const float* __restrict__ src,
                              float* __restrict__ dst) {
    int node = (blockIdx.x * blockDim.x + threadIdx.x) >> 5;
    int lane = threadIdx.x & 31;
    if (node >= N_NODES) return;
    int i   = g_ptr[node];
    int end = g_ptr[node + 1];
    float4 a0 = make_float4(0.f, 0.f, 0.f, 0.f);
    float4 a1 = make_float4(0.f, 0.f, 0.f, 0.f);

    // unroll-by-2 for memory-level parallelism
    for (; i + 2 <= end; i += 2) {
        int   r0 = g_srcidx[i],     r1 = g_srcidx[i + 1];
        float w0 = g_wval[i],       w1 = g_wval[i + 1];
        const float4* s0 = reinterpret_cast<const float4*>(src + (size_t)r0 * C);
        const float4* s1 = reinterpret_cast<const float4*>(src + (size_t)r1 * C);
        float4 p0 = s0[lane], p1 = s0[lane + 32];
        float4 q0 = s1[lane], q1 = s1[lane + 32];
        a0.x += w0 * p0.x; a0.y += w0 * p0.y; a0.z += w0 * p0.z; a0.w += w0 * p0.w;
        a1.x += w0 * p1.x; a1.y += w0 * p1.y; a1.z += w0 * p1.z; a1.w += w0 * p1.w;
        a0.x += w1 * q0.x; a0.y += w1 * q0.y; a0.z += w1 * q0.z; a0.w += w1 * q0.w;
        a1.x += w1 * q1.x; a1.y += w1 * q1.y; a1.z += w1 * q1.z; a1.w += w1 * q1.w;
    }
    if (i < end) {
        int r = g_srcidx[i];
        float wv = g_wval[i];
        const float4* s = reinterpret_cast<const float4*>(src + (size_t)r * C);
        float4 p0 = s[lane], p1 = s[lane + 32];
        a0.x += wv * p0.x; a0.y += wv * p0.y; a0.z += wv * p0.z; a0.w += wv * p0.w;
        a1.x += wv * p1.x; a1.y += wv * p1.y; a1.z += wv * p1.z; a1.w += wv * p1.w;
    }
    float4* d = reinterpret_cast<float4*>(dst + (size_t)node * C);
    d[lane]      = a0;
    d[lane + 32] = a1;
}

// out[M,256] = A[M,256] @ W[256,256]^T + bias (64x64 tile, 4x4 micro)
__global__ void gemm_kernel(const float* __restrict__ A,
                            const float* __restrict__ W,
                            const float* __restrict__ bias,
                            float* __restrict__ out) {
    __shared__ float As[16][65];
    __shared__ float Bs[16][65];
    int tid = threadIdx.x;
    int tx = tid & 15;
    int ty = tid >> 4;
    int m0 = blockIdx.x * 64;
    int n0 = blockIdx.y * 64;
    int lm = tid >> 2;
    int lk = (tid & 3) * 4;

    float acc[4][4] = {};

    for (int k0 = 0; k0 < C; k0 += 16) {
        int am = m0 + lm;
        float4 av = make_float4(0.f, 0.f, 0.f, 0.f);
        if (am < N_NODES)
            av = *reinterpret_cast<const float4*>(A + (size_t)am * C + k0 + lk);
        As[lk + 0][lm] = av.x;
        As[lk + 1][lm] = av.y;
        As[lk + 2][lm] = av.z;
        As[lk + 3][lm] = av.w;

        float4 bv = *reinterpret_cast<const float4*>(W + (size_t)(n0 + lm) * C + k0 + lk);
        Bs[lk + 0][lm] = bv.x;
        Bs[lk + 1][lm] = bv.y;
        Bs[lk + 2][lm] = bv.z;
        Bs[lk + 3][lm] = bv.w;
        __syncthreads();

        #pragma unroll
        for (int kk = 0; kk < 16; kk++) {
            float a[4], b[4];
            #pragma unroll
            for (int i = 0; i < 4; i++) a[i] = As[kk][ty * 4 + i];
            #pragma unroll
            for (int j = 0; j < 4; j++) b[j] = Bs[kk][tx * 4 + j];
            #pragma unroll
            for (int i = 0; i < 4; i++)
                #pragma unroll
                for (int j = 0; j < 4; j++)
                    acc[i][j] += a[i] * b[j];
        }
        __syncthreads();
    }

    #pragma unroll
    for (int i = 0; i < 4; i++) {
        int m = m0 + ty * 4 + i;
        if (m >= N_NODES) continue;
        #pragma unroll
        for (int j = 0; j < 4; j++) {
            int n = n0 + tx * 4 + j;
            out[(size_t)m * C + n] = acc[i][j] + bias[n];
        }
    }
}

// ---------------- launch ----------------

extern "C" void kernel_launch(void* const* d_in, const int* in_sizes, int n_in,
                              void* d_out, int out_size) {
    const float* x  = (const float*)d_in[0];
    const void*  ei = d_in[1];
    const float* w  = (const float*)d_in[2];
    const float* lw = (const float*)d_in[3];
    const float* lb = (const float*)d_in[4];
    float* out = (float*)d_out;

    float *bufA, *bufB, *deg;
    int *cnt;
    cudaGetSymbolAddress((void**)&bufA, g_bufA);
    cudaGetSymbolAddress((void**)&bufB, g_bufB);
    cudaGetSymbolAddress((void**)&deg,  g_deg);
    cudaGetSymbolAddress((void**)&cnt,  g_cnt);

    const int T = 256;

    // CSR build
    detect_kernel<<<1, 256>>>(ei);
    zero_f<<<40, T>>>(deg, N_NODES);
    zero_i<<<40, T>>>(cnt, N_NODES);
    extract_kernel<<<(EDGES + T - 1) / T, T>>>(ei, w);
    dis_kernel<<<(N_NODES + T - 1) / T, T>>>();
    scan_kernel<<<1, 1024>>>();
    fill_kernel<<<(EDGES + T - 1) / T, T>>>(w);

    // normalize -> bufA
    normalize_kernel<<<(N_NODES * 32 + T - 1) / T, T>>>(x);

    // hop 1: bufA -> bufB ; hop 2: bufB -> bufA  (atomic-free gathers)
    int ggrid = (N_NODES * 32 + T - 1) / T;
    gather_kernel<<<ggrid, T>>>(bufA, bufB);
    gather_kernel<<<ggrid, T>>>(bufB, bufA);

    // linear
    dim3 lgrid((N_NODES + 63) / 64, C / 64);
    gemm_kernel<<<lgrid, T>>>(bufA, lw, lb, out);
}

// round 4
// speedup vs baseline: 4.0003x; 1.1599x over previous
#include <cuda_runtime.h>
#include <cuda_fp16.h>

#define N_NODES 20000
#define EDGES   640000
#define C       256

// ---------------- scratch ----------------
__device__ __half g_hA[N_NODES * C];    // fp16 hop sources (x_norm)
__device__ __half g_hB[N_NODES * C];    // fp16 hop1 output
__device__ float  g_bufA[N_NODES * C];  // fp32 hop2 output (GEMM input)
__device__ float  g_deg[N_NODES];
__device__ int    g_cnt[N_NODES];
__device__ int    g_ptr[N_NODES + 1];
__device__ int    g_cursor[N_NODES];
__device__ int    g_srcidx[EDGES];
__device__ float  g_wval[EDGES];
__device__ int    g_row[EDGES];
__device__ int    g_col[EDGES];
__device__ int    g_idx64;

// ---------------- setup kernels ----------------

__global__ void zero_f(float* __restrict__ p, int n) {
    int i = blockIdx.x * blockDim.x + threadIdx.x;
    for (int s = gridDim.x * blockDim.x; i < n; i += s) p[i] = 0.0f;
}
__global__ void zero_i(int* __restrict__ p, int n) {
    int i = blockIdx.x * blockDim.x + threadIdx.x;
    for (int s = gridDim.x * blockDim.x; i < n; i += s) p[i] = 0;
}

__global__ void detect_kernel(const void* ei) {
    __shared__ int bad;
    if (threadIdx.x == 0) bad = 0;
    __syncthreads();
    const long long* p = (const long long*)ei;
    for (int i = threadIdx.x; i < 2048; i += blockDim.x) {
        long long v = p[i];
        if (v < 0 || v >= N_NODES) bad = 1;
    }
    __syncthreads();
    if (threadIdx.x == 0) g_idx64 = bad ? 0 : 1;
}

__global__ void extract_kernel(const void* ei, const float* __restrict__ w) {
    int e = blockIdx.x * blockDim.x + threadIdx.x;
    if (e >= EDGES) return;
    long long r, c;
    if (g_idx64) {
        r = ((const long long*)ei)[e];
        c = ((const long long*)ei)[EDGES + e];
    } else {
        r = ((const int*)ei)[e];
        c = ((const int*)ei)[EDGES + e];
    }
    if (r < 0 || r >= N_NODES) r = 0;
    if (c < 0 || c >= N_NODES) c = 0;
    g_row[e] = (int)r;
    g_col[e] = (int)c;
    atomicAdd(&g_deg[c], w[e]);
    atomicAdd(&g_cnt[c], 1);
}

__global__ void dis_kernel() {
    int i = blockIdx.x * blockDim.x + threadIdx.x;
    if (i >= N_NODES) return;
    float d = g_deg[i];
    g_deg[i] = (d > 0.0f) ? rsqrtf(d) : 0.0f;
}

__global__ void scan_kernel() {
    __shared__ int wsum[32];
    __shared__ int s_running;
    int tid = threadIdx.x;
    int lane = tid & 31, wid = tid >> 5;
    if (tid == 0) s_running = 0;
    __syncthreads();
    for (int base = 0; base < N_NODES; base += 1024) {
        int i = base + tid;
        int v = (i < N_NODES) ? g_cnt[i] : 0;
        int s = v;
        #pragma unroll
        for (int o = 1; o < 32; o <<= 1) {
            int t = __shfl_up_sync(0xffffffffu, s, o);
            if (lane >= o) s += t;
        }
        if (lane == 31) wsum[wid] = s;
        __syncthreads();
        if (wid == 0) {
            int ws = wsum[lane];
            #pragma unroll
            for (int o = 1; o < 32; o <<= 1) {
                int t = __shfl_up_sync(0xffffffffu, ws, o);
                if (lane >= o) ws += t;
            }
            wsum[lane] = ws;
        }
        __syncthreads();
        int excl = s_running + s - v + (wid > 0 ? wsum[wid - 1] : 0);
        if (i < N_NODES) {
            g_ptr[i] = excl;
            g_cursor[i] = excl;
        }
        __syncthreads();
        if (tid == 0) s_running += wsum[31];
        __syncthreads();
    }
    if (tid == 0) g_ptr[N_NODES] = s_running;
}

__global__ void fill_kernel(const float* __restrict__ w) {
    int e = blockIdx.x * blockDim.x + threadIdx.x;
    if (e >= EDGES) return;
    int r = g_row[e], c = g_col[e];
    int pos = atomicAdd(&g_cursor[c], 1);
    g_srcidx[pos] = r;
    g_wval[pos]  = g_deg[r] * w[e] * g_deg[c];
}

// warp per row: L2-normalize x -> g_hA (fp16)
__global__ void normalize_kernel(const float* __restrict__ x) {
    int warp = (blockIdx.x * blockDim.x + threadIdx.x) >> 5;
    int lane = threadIdx.x & 31;
    if (warp >= N_NODES) return;
    const float4* xr = reinterpret_cast<const float4*>(x + (size_t)warp * C);
    float4 v0 = xr[lane];
    float4 v1 = xr[lane + 32];
    float ss = v0.x*v0.x + v0.y*v0.y + v0.z*v0.z + v0.w*v0.w
             + v1.x*v1.x + v1.y*v1.y + v1.z*v1.z + v1.w*v1.w;
    #pragma unroll
    for (int o = 16; o; o >>= 1) ss += __shfl_xor_sync(0xffffffffu, ss, o);
    float inv = 1.0f / fmaxf(sqrtf(ss), 1e-12f);
    // lane writes 8 consecutive halfs (pair layout: lane*4 floats from v0 block,
    // lane*4+128 from v1 block) -- keep a simple layout: 8 contiguous at lane*8
    // by re-reading contiguously instead:
    const float* xf = x + (size_t)warp * C;
    __half2 h[4];
    #pragma unroll
    for (int k = 0; k < 4; k++) {
        float a = xf[lane * 8 + k * 2]     * inv;
        float b = xf[lane * 8 + k * 2 + 1] * inv;
        h[k] = __floats2half2_rn(a, b);
    }
    *reinterpret_cast<uint4*>(g_hA + (size_t)warp * C + lane * 8) =
        *reinterpret_cast<uint4*>(h);
}

// warp per target node: fp16 src rows, fp32 accumulate.
// Each lane owns 8 consecutive channels (lane*8 .. lane*8+7) = one uint4 of halfs.
template <int OUT_FP16>
__global__ void gather_kernel(const __half* __restrict__ src, void* __restrict__ dstv) {
    int node = (blockIdx.x * blockDim.x + threadIdx.x) >> 5;
    int lane = threadIdx.x & 31;
    if (node >= N_NODES) return;
    int i   = g_ptr[node];
    int end = g_ptr[node + 1];
    float acc[8] = {};

    // 4-edge unroll for MLP
    for (; i + 4 <= end; i += 4) {
        int   r0 = g_srcidx[i],   r1 = g_srcidx[i+1], r2 = g_srcidx[i+2], r3 = g_srcidx[i+3];
        float w0 = g_wval[i],     w1 = g_wval[i+1],   w2 = g_wval[i+2],   w3 = g_wval[i+3];
        uint4 v0 = *reinterpret_cast<const uint4*>(src + (size_t)r0 * C + lane * 8);
        uint4 v1 = *reinterpret_cast<const uint4*>(src + (size_t)r1 * C + lane * 8);
        uint4 v2 = *reinterpret_cast<const uint4*>(src + (size_t)r2 * C + lane * 8);
        uint4 v3 = *reinterpret_cast<const uint4*>(src + (size_t)r3 * C + lane * 8);
        const __half2* h0 = reinterpret_cast<const __half2*>(&v0);
        const __half2* h1 = reinterpret_cast<const __half2*>(&v1);
        const __half2* h2 = reinterpret_cast<const __half2*>(&v2);
        const __half2* h3 = reinterpret_cast<const __half2*>(&v3);
        #pragma unroll
        for (int k = 0; k < 4; k++) {
            float2 f0 = __half22float2(h0[k]);
            float2 f1 = __half22float2(h1[k]);
            float2 f2 = __half22float2(h2[k]);
            float2 f3 = __half22float2(h3[k]);
            acc[2*k]   += w0 * f0.x + w1 * f1.x + w2 * f2.x + w3 * f3.x;
            acc[2*k+1] += w0 * f0.y + w1 * f1.y + w2 * f2.y + w3 * f3.y;
        }
    }
    for (; i < end; i++) {
        int r = g_srcidx[i];
        float wv = g_wval[i];
        uint4 v = *reinterpret_cast<const uint4*>(src + (size_t)r * C + lane * 8);
        const __half2* h = reinterpret_cast<const __half2*>(&v);
        #pragma unroll
        for (int k = 0; k < 4; k++) {
            float2 f = __half22float2(h[k]);
            acc[2*k]   += wv * f.x;
            acc[2*k+1] += wv * f.y;
        }
    }

    if (OUT_FP16) {
        __half2 h[4];
        #pragma unroll
        for (int k = 0; k < 4; k++) h[k] = __floats2half2_rn(acc[2*k], acc[2*k+1]);
        *reinterpret_cast<uint4*>((__half*)dstv + (size_t)node * C + lane * 8) =
            *reinterpret_cast<uint4*>(h);
    } else {
        float* d = (float*)dstv + (size_t)node * C + lane * 8;
        *reinterpret_cast<float4*>(d)     = make_float4(acc[0], acc[1], acc[2], acc[3]);
        *reinterpret_cast<float4*>(d + 4) = make_float4(acc[4], acc[5], acc[6], acc[7]);
    }
}

// out[M,256] = A[M,256] @ W[256,256]^T + bias
// 128x128 tile, BK=16, 256 threads, 8x8 micro-tile
__global__ void gemm_kernel(const float* __restrict__ A,
                            const float* __restrict__ W,
                            const float* __restrict__ bias,
                            float* __restrict__ out) {
    __shared__ float As[16][132];  // As[k][m], stride 132 floats (16B-aligned rows)
    __shared__ float Bs[16][132];  // Bs[k][n] = W[n][k]
    int tid = threadIdx.x;
    int tx = tid & 15;       // n group
    int ty = tid >> 4;       // m group
    int m0 = blockIdx.x * 128;
    int n0 = blockIdx.y * 128;

    float acc[8][8] = {};

    for (int k0 = 0; k0 < C; k0 += 16) {
        // load 128x16 A tile and 128x16 B tile (each thread: 2 float4 per tile)
        #pragma unroll
        for (int ch = 0; ch < 2; ch++) {
            int lin = tid + ch * 256;        // 0..511
            int row = lin >> 2;              // 0..127
            int kc  = (lin & 3) * 4;         // 0,4,8,12
            int am = m0 + row;
            float4 av = make_float4(0.f, 0.f, 0.f, 0.f);
            if (am < N_NODES)
                av = *reinterpret_cast<const float4*>(A + (size_t)am * C + k0 + kc);
            As[kc + 0][row] = av.x;
            As[kc + 1][row] = av.y;
            As[kc + 2][row] = av.z;
            As[kc + 3][row] = av.w;
            float4 bv = *reinterpret_cast<const float4*>(W + (size_t)(n0 + row) * C + k0 + kc);
            Bs[kc + 0][row] = bv.x;
            Bs[kc + 1][row] = bv.y;
            Bs[kc + 2][row] = bv.z;
            Bs[kc + 3][row] = bv.w;
        }
        __syncthreads();

        #pragma unroll
        for (int kk = 0; kk < 16; kk++) {
            float a[8], b[8];
            *reinterpret_cast<float4*>(a)     = *reinterpret_cast<const float4*>(&As[kk][ty * 8]);
            *reinterpret_cast<float4*>(a + 4) = *reinterpret_cast<const float4*>(&As[kk][ty * 8 + 4]);
            *reinterpret_cast<float4*>(b)     = *reinterpret_cast<const float4*>(&Bs[kk][tx * 8]);
            *reinterpret_cast<float4*>(b + 4) = *reinterpret_cast<const float4*>(&Bs[kk][tx * 8 + 4]);
            #pragma unroll
            for (int i = 0; i < 8; i++)
                #pragma unroll
                for (int j = 0; j < 8; j++)
                    acc[i][j] += a[i] * b[j];
        }
        __syncthreads();
    }

    #pragma unroll
    for (int i = 0; i < 8; i++) {
        int m = m0 + ty * 8 + i;
        if (m >= N_NODES) continue;
        #pragma unroll
        for (int j = 0; j < 8; j += 4) {
            int n = n0 + tx * 8 + j;
            float4 r = make_float4(acc[i][j]   + bias[n],
                                   acc[i][j+1] + bias[n+1],
                                   acc[i][j+2] + bias[n+2],
                                   acc[i][j+3] + bias[n+3]);
            *reinterpret_cast<float4*>(out + (size_t)m * C + n) = r;
        }
    }
}

// ---------------- launch ----------------

extern "C" void kernel_launch(void* const* d_in, const int* in_sizes, int n_in,
                              void* d_out, int out_size) {
    const float* x  = (const float*)d_in[0];
    const void*  ei = d_in[1];
    const float* w  = (const float*)d_in[2];
    const float* lw = (const float*)d_in[3];
    const float* lb = (const float*)d_in[4];
    float* out = (float*)d_out;

    float *bufA, *deg;
    int *cnt;
    __half *hA, *hB;
    cudaGetSymbolAddress((void**)&bufA, g_bufA);
    cudaGetSymbolAddress((void**)&deg,  g_deg);
    cudaGetSymbolAddress((void**)&cnt,  g_cnt);
    cudaGetSymbolAddress((void**)&hA,   g_hA);
    cudaGetSymbolAddress((void**)&hB,   g_hB);

    const int T = 256;

    // CSR build
    detect_kernel<<<1, 256>>>(ei);
    zero_f<<<40, T>>>(deg, N_NODES);
    zero_i<<<40, T>>>(cnt, N_NODES);
    extract_kernel<<<(EDGES + T - 1) / T, T>>>(ei, w);
    dis_kernel<<<(N_NODES + T - 1) / T, T>>>();
    scan_kernel<<<1, 1024>>>();
    fill_kernel<<<(EDGES + T - 1) / T, T>>>(w);

    // normalize -> hA (fp16)
    normalize_kernel<<<(N_NODES * 32 + T - 1) / T, T>>>(x);

    // hops: hA -> hB (fp16), hB -> bufA (fp32)
    int ggrid = (N_NODES * 32 + T - 1) / T;
    gather_kernel<1><<<ggrid, T>>>(hA, hB);
    gather_kernel<0><<<ggrid, T>>>(hB, bufA);

    // linear
    dim3 lgrid((N_NODES + 127) / 128, C / 128);
    gemm_kernel<<<lgrid, T>>>(bufA, lw, lb, out);
}

// round 5
// speedup vs baseline: 4.5326x; 1.1331x over previous
#include <cuda_runtime.h>
#include <cuda_fp16.h>

#define N_NODES 20000
#define EDGES   640000
#define C       256

// ---------------- scratch ----------------
__device__ __half g_hA[N_NODES * C];    // x_norm fp16, later hop2 output (GEMM A)
__device__ __half g_hB[N_NODES * C];    // hop1 output fp16
__device__ __half g_hW[C * C];          // fp16 weights [n][k]
__device__ float  g_deg[N_NODES];
__device__ int    g_cnt[N_NODES];
__device__ int    g_ptr[N_NODES + 1];
__device__ int    g_cursor[N_NODES];
__device__ int    g_srcidx[EDGES];
__device__ float  g_wval[EDGES];
__device__ int    g_row[EDGES];
__device__ int    g_col[EDGES];
__device__ int    g_idx64;

// ---------------- setup kernels ----------------

__global__ void zero_deg_cnt() {
    int i = blockIdx.x * blockDim.x + threadIdx.x;
    if (i < N_NODES) { g_deg[i] = 0.0f; g_cnt[i] = 0; }
}

__global__ void detect_kernel(const void* ei) {
    __shared__ int bad;
    if (threadIdx.x == 0) bad = 0;
    __syncthreads();
    const long long* p = (const long long*)ei;
    for (int i = threadIdx.x; i < 2048; i += blockDim.x) {
        long long v = p[i];
        if (v < 0 || v >= N_NODES) bad = 1;
    }
    __syncthreads();
    if (threadIdx.x == 0) g_idx64 = bad ? 0 : 1;
}

__global__ void extract_kernel(const void* ei, const float* __restrict__ w) {
    int e = blockIdx.x * blockDim.x + threadIdx.x;
    if (e >= EDGES) return;
    long long r, c;
    if (g_idx64) {
        r = ((const long long*)ei)[e];
        c = ((const long long*)ei)[EDGES + e];
    } else {
        r = ((const int*)ei)[e];
        c = ((const int*)ei)[EDGES + e];
    }
    if (r < 0 || r >= N_NODES) r = 0;
    if (c < 0 || c >= N_NODES) c = 0;
    g_row[e] = (int)r;
    g_col[e] = (int)c;
    atomicAdd(&g_deg[c], w[e]);
    atomicAdd(&g_cnt[c], 1);
}

__global__ void dis_kernel() {
    int i = blockIdx.x * blockDim.x + threadIdx.x;
    if (i >= N_NODES) return;
    float d = g_deg[i];
    g_deg[i] = (d > 0.0f) ? rsqrtf(d) : 0.0f;
}

__global__ void scan_kernel() {
    __shared__ int wsum[32];
    __shared__ int s_running;
    int tid = threadIdx.x;
    int lane = tid & 31, wid = tid >> 5;
    if (tid == 0) s_running = 0;
    __syncthreads();
    for (int base = 0; base < N_NODES; base += 1024) {
        int i = base + tid;
        int v = (i < N_NODES) ? g_cnt[i] : 0;
        int s = v;
        #pragma unroll
        for (int o = 1; o < 32; o <<= 1) {
            int t = __shfl_up_sync(0xffffffffu, s, o);
            if (lane >= o) s += t;
        }
        if (lane == 31) wsum[wid] = s;
        __syncthreads();
        if (wid == 0) {
            int ws = wsum[lane];
            #pragma unroll
            for (int o = 1; o < 32; o <<= 1) {
                int t = __shfl_up_sync(0xffffffffu, ws, o);
                if (lane >= o) ws += t;
            }
            wsum[lane] = ws;
        }
        __syncthreads();
        int excl = s_running + s - v + (wid > 0 ? wsum[wid - 1] : 0);
        if (i < N_NODES) {
            g_ptr[i] = excl;
            g_cursor[i] = excl;
        }
        __syncthreads();
        if (tid == 0) s_running += wsum[31];
        __syncthreads();
    }
    if (tid == 0) g_ptr[N_NODES] = s_running;
}

__global__ void fill_kernel(const float* __restrict__ w) {
    int e = blockIdx.x * blockDim.x + threadIdx.x;
    if (e >= EDGES) return;
    int r = g_row[e], c = g_col[e];
    int pos = atomicAdd(&g_cursor[c], 1);
    g_srcidx[pos] = r;
    g_wval[pos]  = g_deg[r] * w[e] * g_deg[c];
}

// W (fp32 [n][k]) -> fp16
__global__ void convw_kernel(const float* __restrict__ W) {
    int i = (blockIdx.x * blockDim.x + threadIdx.x) * 8;
    if (i >= C * C) return;
    __half2 h[4];
    #pragma unroll
    for (int k = 0; k < 4; k++)
        h[k] = __floats2half2_rn(W[i + 2*k], W[i + 2*k + 1]);
    *reinterpret_cast<uint4*>(g_hW + i) = *reinterpret_cast<uint4*>(h);
}

// warp per row: L2-normalize x -> g_hA (fp16)
__global__ void normalize_kernel(const float* __restrict__ x) {
    int warp = (blockIdx.x * blockDim.x + threadIdx.x) >> 5;
    int lane = threadIdx.x & 31;
    if (warp >= N_NODES) return;
    const float4* xr = reinterpret_cast<const float4*>(x + (size_t)warp * C);
    float4 v0 = xr[lane * 2];
    float4 v1 = xr[lane * 2 + 1];
    float ss = v0.x*v0.x + v0.y*v0.y + v0.z*v0.z + v0.w*v0.w
             + v1.x*v1.x + v1.y*v1.y + v1.z*v1.z + v1.w*v1.w;
    #pragma unroll
    for (int o = 16; o; o >>= 1) ss += __shfl_xor_sync(0xffffffffu, ss, o);
    float inv = 1.0f / fmaxf(sqrtf(ss), 1e-12f);
    __half2 h[4];
    h[0] = __floats2half2_rn(v0.x * inv, v0.y * inv);
    h[1] = __floats2half2_rn(v0.z * inv, v0.w * inv);
    h[2] = __floats2half2_rn(v1.x * inv, v1.y * inv);
    h[3] = __floats2half2_rn(v1.z * inv, v1.w * inv);
    *reinterpret_cast<uint4*>(g_hA + (size_t)warp * C + lane * 8) =
        *reinterpret_cast<uint4*>(h);
}

// warp per target node: fp16 src rows, fp32 accumulate, fp16 out
__global__ void gather_kernel(const __half* __restrict__ src, __half* __restrict__ dst) {
    int node = (blockIdx.x * blockDim.x + threadIdx.x) >> 5;
    int lane = threadIdx.x & 31;
    if (node >= N_NODES) return;
    int i   = g_ptr[node];
    int end = g_ptr[node + 1];
    float acc[8] = {};

    for (; i + 4 <= end; i += 4) {
        int   r0 = g_srcidx[i],   r1 = g_srcidx[i+1], r2 = g_srcidx[i+2], r3 = g_srcidx[i+3];
        float w0 = g_wval[i],     w1 = g_wval[i+1],   w2 = g_wval[i+2],   w3 = g_wval[i+3];
        uint4 v0 = *reinterpret_cast<const uint4*>(src + (size_t)r0 * C + lane * 8);
        uint4 v1 = *reinterpret_cast<const uint4*>(src + (size_t)r1 * C + lane * 8);
        uint4 v2 = *reinterpret_cast<const uint4*>(src + (size_t)r2 * C + lane * 8);
        uint4 v3 = *reinterpret_cast<const uint4*>(src + (size_t)r3 * C + lane * 8);
        const __half2* h0 = reinterpret_cast<const __half2*>(&v0);
        const __half2* h1 = reinterpret_cast<const __half2*>(&v1);
        const __half2* h2 = reinterpret_cast<const __half2*>(&v2);
        const __half2* h3 = reinterpret_cast<const __half2*>(&v3);
        #pragma unroll
        for (int k = 0; k < 4; k++) {
            float2 f0 = __half22float2(h0[k]);
            float2 f1 = __half22float2(h1[k]);
            float2 f2 = __half22float2(h2[k]);
            float2 f3 = __half22float2(h3[k]);
            acc[2*k]   += w0 * f0.x + w1 * f1.x + w2 * f2.x + w3 * f3.x;
            acc[2*k+1] += w0 * f0.y + w1 * f1.y + w2 * f2.y + w3 * f3.y;
        }
    }
    for (; i < end; i++) {
        int r = g_srcidx[i];
        float wv = g_wval[i];
        uint4 v = *reinterpret_cast<const uint4*>(src + (size_t)r * C + lane * 8);
        const __half2* h = reinterpret_cast<const __half2*>(&v);
        #pragma unroll
        for (int k = 0; k < 4; k++) {
            float2 f = __half22float2(h[k]);
            acc[2*k]   += wv * f.x;
            acc[2*k+1] += wv * f.y;
        }
    }

    __half2 h[4];
    #pragma unroll
    for (int k = 0; k < 4; k++) h[k] = __floats2half2_rn(acc[2*k], acc[2*k+1]);
    *reinterpret_cast<uint4*>(dst + (size_t)node * C + lane * 8) =
        *reinterpret_cast<uint4*>(h);
}

// ---------------- tensor-core GEMM ----------------
// out[M,256] = A[M,256](fp16) @ W[256,256]^T(fp16) + bias, fp32 accum.
// Block: 256 thr (8 warps), tile M=128 N=64, BK=64.
// Warp: 32x32 (2 m-subtiles x 4 n-subtiles of m16n8k16).
#define BK 64

__global__ void hgemm_kernel(const __half* __restrict__ A,
                             const float* __restrict__ bias,
                             float* __restrict__ out) {
    __shared__ __half As[128 * BK];  // swizzled: row*64 + (chunk^(row&7))*8
    __shared__ __half Bs[64 * BK];

    int tid = threadIdx.x;
    int lane = tid & 31;
    int warp = tid >> 5;
    int wm = warp & 3;          // 4 m-groups of 32
    int wn = warp >> 2;         // 2 n-groups of 32
    int g  = lane >> 2;         // 0..7
    int tg = lane & 3;          // 0..3

    int m0 = blockIdx.x * 128;
    int n0 = blockIdx.y * 64;

    float d[2][4][4] = {};      // [m-sub][n-sub][4 f32]

    for (int ks = 0; ks < C / BK; ks++) {
        int k0 = ks * BK;
        // load A tile 128xBK (1024 uint4, 4/thread)
        #pragma unroll
        for (int i = 0; i < 4; i++) {
            int lin = tid + i * 256;
            int row = lin >> 3;
            int ch  = lin & 7;
            int gm  = m0 + row;
            uint4 v = make_uint4(0, 0, 0, 0);
            if (gm < N_NODES)
                v = *reinterpret_cast<const uint4*>(A + (size_t)gm * C + k0 + ch * 8);
            *reinterpret_cast<uint4*>(&As[row * BK + ((ch ^ (row & 7)) * 8)]) = v;
        }
        // load B tile 64xBK (512 uint4, 2/thread): Bs[n][k] = W[n0+n][k0+k]
        #pragma unroll
        for (int i = 0; i < 2; i++) {
            int lin = tid + i * 256;
            int row = lin >> 3;
            int ch  = lin & 7;
            uint4 v = *reinterpret_cast<const uint4*>(g_hW + (size_t)(n0 + row) * C + k0 + ch * 8);
            *reinterpret_cast<uint4*>(&Bs[row * BK + ((ch ^ (row & 7)) * 8)]) = v;
        }
        __syncthreads();

        #pragma unroll
        for (int kc = 0; kc < BK / 16; kc++) {
            // A fragments for 2 m-subtiles
            unsigned a[2][4];
            #pragma unroll
            for (int sm = 0; sm < 2; sm++) {
                int r0 = wm * 32 + sm * 16 + g;
                int r1 = r0 + 8;
                int x0 = (kc * 2) ^ (r0 & 7);
                int x1 = (kc * 2) ^ (r1 & 7);
                a[sm][0] = *reinterpret_cast<const unsigned*>(&As[r0 * BK + x0 * 8 + tg * 2]);
                a[sm][1] = *reinterpret_cast<const unsigned*>(&As[r1 * BK + x1 * 8 + tg * 2]);
                a[sm][2] = *reinterpret_cast<const unsigned*>(&As[r0 * BK + ((kc * 2 + 1) ^ (r0 & 7)) * 8 + tg * 2]);
                a[sm][3] = *reinterpret_cast<const unsigned*>(&As[r1 * BK + ((kc * 2 + 1) ^ (r1 & 7)) * 8 + tg * 2]);
            }
            #pragma unroll
            for (int sn = 0; sn < 4; sn++) {
                int nr = wn * 32 + sn * 8 + g;
                unsigned b0 = *reinterpret_cast<const unsigned*>(&Bs[nr * BK + ((kc * 2) ^ (nr & 7)) * 8 + tg * 2]);
                unsigned b1 = *reinterpret_cast<const unsigned*>(&Bs[nr * BK + ((kc * 2 + 1) ^ (nr & 7)) * 8 + tg * 2]);
                #pragma unroll
                for (int sm = 0; sm < 2; sm++) {
                    asm volatile(
                        "mma.sync.aligned.m16n8k16.row.col.f32.f16.f16.f32 "
                        "{%0,%1,%2,%3}, {%4,%5,%6,%7}, {%8,%9}, {%0,%1,%2,%3};"
                        : "+f"(d[sm][sn][0]), "+f"(d[sm][sn][1]),
                          "+f"(d[sm][sn][2]), "+f"(d[sm][sn][3])
                        : "r"(a[sm][0]), "r"(a[sm][1]), "r"(a[sm][2]), "r"(a[sm][3]),
                          "r"(b0), "r"(b1));
                }
            }
        }
        __syncthreads();
    }

    // epilogue
    #pragma unroll
    for (int sm = 0; sm < 2; sm++) {
        #pragma unroll
        for (int sn = 0; sn < 4; sn++) {
            int col = n0 + wn * 32 + sn * 8 + tg * 2;
            float b0 = bias[col], b1 = bias[col + 1];
            int r0 = m0 + wm * 32 + sm * 16 + g;
            if (r0 < N_NODES) {
                float2 v = make_float2(d[sm][sn][0] + b0, d[sm][sn][1] + b1);
                *reinterpret_cast<float2*>(out + (size_t)r0 * C + col) = v;
            }
            int r1 = r0 + 8;
            if (r1 < N_NODES) {
                float2 v = make_float2(d[sm][sn][2] + b0, d[sm][sn][3] + b1);
                *reinterpret_cast<float2*>(out + (size_t)r1 * C + col) = v;
            }
        }
    }
}

// ---------------- launch ----------------

extern "C" void kernel_launch(void* const* d_in, const int* in_sizes, int n_in,
                              void* d_out, int out_size) {
    const float* x  = (const float*)d_in[0];
    const void*  ei = d_in[1];
    const float* w  = (const float*)d_in[2];
    const float* lw = (const float*)d_in[3];
    const float* lb = (const float*)d_in[4];
    float* out = (float*)d_out;

    __half *hA, *hB;
    cudaGetSymbolAddress((void**)&hA, g_hA);
    cudaGetSymbolAddress((void**)&hB, g_hB);

    const int T = 256;

    // CSR build
    detect_kernel<<<1, 256>>>(ei);
    zero_deg_cnt<<<(N_NODES + T - 1) / T, T>>>();
    extract_kernel<<<(EDGES + T - 1) / T, T>>>(ei, w);
    dis_kernel<<<(N_NODES + T - 1) / T, T>>>();
    scan_kernel<<<1, 1024>>>();
    fill_kernel<<<(EDGES + T - 1) / T, T>>>(w);

    // W -> fp16, x -> normalized fp16
    convw_kernel<<<(C * C / 8 + T - 1) / T, T>>>(lw);
    normalize_kernel<<<(N_NODES * 32 + T - 1) / T, T>>>(x);

    // hops: hA -> hB -> hA (fp16 all the way)
    int ggrid = (N_NODES * 32 + T - 1) / T;
    gather_kernel<<<ggrid, T>>>(hA, hB);
    gather_kernel<<<ggrid, T>>>(hB, hA);

    // tensor-core linear
    dim3 lgrid((N_NODES + 127) / 128, C / 64);
    hgemm_kernel<<<lgrid, T>>>(hA, lb, out);
}

// round 6
// speedup vs baseline: 7.1169x; 1.5701x over previous
#include <cuda_runtime.h>
#include <cuda_fp16.h>

#define N_NODES 20000
#define EDGES   640000
#define C       256

// ---------------- scratch ----------------
__device__ __half g_hA[N_NODES * C];    // x_norm fp16, later hop2 output (GEMM A)
__device__ __half g_hB[N_NODES * C];    // hop1 output fp16
__device__ __half g_hW[C * C];          // fp16 weights [n][k]
__device__ float  g_deg[N_NODES];
__device__ int    g_cnt[N_NODES];
__device__ int    g_ptr[N_NODES + 1];
__device__ int    g_cursor[N_NODES];
__device__ int    g_srcidx[EDGES];
__device__ float  g_wval[EDGES];
__device__ int    g_row[EDGES];
__device__ int    g_col[EDGES];
__device__ int    g_idx64;

// ---------------- setup kernels ----------------

// fused: zero deg/cnt (all blocks) + int64/int32 detection (block 0)
__global__ void init_kernel(const void* ei) {
    int i = blockIdx.x * blockDim.x + threadIdx.x;
    for (int s = gridDim.x * blockDim.x; i < N_NODES; i += s) {
        g_deg[i] = 0.0f;
        g_cnt[i] = 0;
    }
    if (blockIdx.x == 0) {
        __shared__ int bad;
        if (threadIdx.x == 0) bad = 0;
        __syncthreads();
        const long long* p = (const long long*)ei;
        for (int k = threadIdx.x; k < 2048; k += blockDim.x) {
            long long v = p[k];
            if (v < 0 || v >= N_NODES) bad = 1;
        }
        __syncthreads();
        if (threadIdx.x == 0) g_idx64 = bad ? 0 : 1;
    }
}

__global__ void extract_kernel(const void* ei, const float* __restrict__ w) {
    int e = blockIdx.x * blockDim.x + threadIdx.x;
    if (e >= EDGES) return;
    long long r, c;
    if (g_idx64) {
        r = ((const long long*)ei)[e];
        c = ((const long long*)ei)[EDGES + e];
    } else {
        r = ((const int*)ei)[e];
        c = ((const int*)ei)[EDGES + e];
    }
    if (r < 0 || r >= N_NODES) r = 0;
    if (c < 0 || c >= N_NODES) c = 0;
    g_row[e] = (int)r;
    g_col[e] = (int)c;
    atomicAdd(&g_deg[c], w[e]);
    atomicAdd(&g_cnt[c], 1);
}

// fused: deg -> deg^-1/2 transform, then exclusive scan of g_cnt -> g_ptr/g_cursor.
// Single block, 1024 threads, int4-vectorized scan (4 elems/thread/sweep).
__global__ void scan_kernel() {
    __shared__ int wsum[32];
    __shared__ int s_running;
    int tid = threadIdx.x;
    int lane = tid & 31, wid = tid >> 5;

    // dis transform
    for (int i = tid; i < N_NODES; i += 1024) {
        float d = g_deg[i];
        g_deg[i] = (d > 0.0f) ? rsqrtf(d) : 0.0f;
    }
    if (tid == 0) s_running = 0;
    __syncthreads();

    // scan: 5000 int4 elements, 1024 threads -> 5 sweeps
    const int NV = N_NODES / 4;   // 5000
    for (int base = 0; base < NV; base += 1024) {
        int iv = base + tid;
        int4 v = make_int4(0, 0, 0, 0);
        if (iv < NV) v = reinterpret_cast<const int4*>(g_cnt)[iv];
        int lsum = v.x + v.y + v.z + v.w;
        int s = lsum;
        #pragma unroll
        for (int o = 1; o < 32; o <<= 1) {
            int t = __shfl_up_sync(0xffffffffu, s, o);
            if (lane >= o) s += t;
        }
        if (lane == 31) wsum[wid] = s;
        __syncthreads();
        if (wid == 0) {
            int ws = wsum[lane];
            #pragma unroll
            for (int o = 1; o < 32; o <<= 1) {
                int t = __shfl_up_sync(0xffffffffu, ws, o);
                if (lane >= o) ws += t;
            }
            wsum[lane] = ws;
        }
        __syncthreads();
        int excl = s_running + s - lsum + (wid > 0 ? wsum[wid - 1] : 0);
        if (iv < NV) {
            int4 p;
            p.x = excl;
            p.y = p.x + v.x;
            p.z = p.y + v.y;
            p.w = p.z + v.z;
            reinterpret_cast<int4*>(g_ptr)[iv]    = p;
            reinterpret_cast<int4*>(g_cursor)[iv] = p;
        }
        __syncthreads();
        if (tid == 0) s_running += wsum[31];
        __syncthreads();
    }
    if (tid == 0) g_ptr[N_NODES] = s_running;
}

__global__ void fill_kernel(const float* __restrict__ w) {
    int e = blockIdx.x * blockDim.x + threadIdx.x;
    if (e >= EDGES) return;
    int r = g_row[e], c = g_col[e];
    int pos = atomicAdd(&g_cursor[c], 1);
    g_srcidx[pos] = r;
    g_wval[pos]  = g_deg[r] * w[e] * g_deg[c];
}

// fused: blocks [0, NB_NORM) L2-normalize x -> g_hA (warp/row);
//        blocks [NB_NORM, NB_NORM+32) convert W -> fp16.
#define NB_NORM 2500
__global__ void norm_convw_kernel(const float* __restrict__ x,
                                  const float* __restrict__ W) {
    if (blockIdx.x >= NB_NORM) {
        int i = ((blockIdx.x - NB_NORM) * 256 + threadIdx.x) * 8;
        if (i < C * C) {
            __half2 h[4];
            #pragma unroll
            for (int k = 0; k < 4; k++)
                h[k] = __floats2half2_rn(W[i + 2*k], W[i + 2*k + 1]);
            *reinterpret_cast<uint4*>(g_hW + i) = *reinterpret_cast<uint4*>(h);
        }
        return;
    }
    int warp = (blockIdx.x * blockDim.x + threadIdx.x) >> 5;
    int lane = threadIdx.x & 31;
    if (warp >= N_NODES) return;
    const float4* xr = reinterpret_cast<const float4*>(x + (size_t)warp * C);
    float4 v0 = xr[lane * 2];
    float4 v1 = xr[lane * 2 + 1];
    float ss = v0.x*v0.x + v0.y*v0.y + v0.z*v0.z + v0.w*v0.w
             + v1.x*v1.x + v1.y*v1.y + v1.z*v1.z + v1.w*v1.w;
    #pragma unroll
    for (int o = 16; o; o >>= 1) ss += __shfl_xor_sync(0xffffffffu, ss, o);
    float inv = 1.0f / fmaxf(sqrtf(ss), 1e-12f);
    __half2 h[4];
    h[0] = __floats2half2_rn(v0.x * inv, v0.y * inv);
    h[1] = __floats2half2_rn(v0.z * inv, v0.w * inv);
    h[2] = __floats2half2_rn(v1.x * inv, v1.y * inv);
    h[3] = __floats2half2_rn(v1.z * inv, v1.w * inv);
    *reinterpret_cast<uint4*>(g_hA + (size_t)warp * C + lane * 8) =
        *reinterpret_cast<uint4*>(h);
}

// warp per target node: fp16 src rows, fp32 accumulate, fp16 out. 8-edge unroll.
__global__ void gather_kernel(const __half* __restrict__ src, __half* __restrict__ dst) {
    int node = (blockIdx.x * blockDim.x + threadIdx.x) >> 5;
    int lane = threadIdx.x & 31;
    if (node >= N_NODES) return;
    int i   = g_ptr[node];
    int end = g_ptr[node + 1];
    float acc[8] = {};

    for (; i + 8 <= end; i += 8) {
        int r[8]; float wv[8]; uint4 v[8];
        #pragma unroll
        for (int u = 0; u < 8; u++) { r[u] = g_srcidx[i + u]; wv[u] = g_wval[i + u]; }
        #pragma unroll
        for (int u = 0; u < 8; u++)
            v[u] = *reinterpret_cast<const uint4*>(src + (size_t)r[u] * C + lane * 8);
        #pragma unroll
        for (int u = 0; u < 8; u++) {
            const __half2* h = reinterpret_cast<const __half2*>(&v[u]);
            #pragma unroll
            for (int k = 0; k < 4; k++) {
                float2 f = __half22float2(h[k]);
                acc[2*k]   += wv[u] * f.x;
                acc[2*k+1] += wv[u] * f.y;
            }
        }
    }
    for (; i + 2 <= end; i += 2) {
        int   r0 = g_srcidx[i],  r1 = g_srcidx[i+1];
        float w0 = g_wval[i],    w1 = g_wval[i+1];
        uint4 v0 = *reinterpret_cast<const uint4*>(src + (size_t)r0 * C + lane * 8);
        uint4 v1 = *reinterpret_cast<const uint4*>(src + (size_t)r1 * C + lane * 8);
        const __half2* h0 = reinterpret_cast<const __half2*>(&v0);
        const __half2* h1 = reinterpret_cast<const __half2*>(&v1);
        #pragma unroll
        for (int k = 0; k < 4; k++) {
            float2 f0 = __half22float2(h0[k]);
            float2 f1 = __half22float2(h1[k]);
            acc[2*k]   += w0 * f0.x + w1 * f1.x;
            acc[2*k+1] += w0 * f0.y + w1 * f1.y;
        }
    }
    if (i < end) {
        int r = g_srcidx[i];
        float wv = g_wval[i];
        uint4 v = *reinterpret_cast<const uint4*>(src + (size_t)r * C + lane * 8);
        const __half2* h = reinterpret_cast<const __half2*>(&v);
        #pragma unroll
        for (int k = 0; k < 4; k++) {
            float2 f = __half22float2(h[k]);
            acc[2*k]   += wv * f.x;
            acc[2*k+1] += wv * f.y;
        }
    }

    __half2 h[4];
    #pragma unroll
    for (int k = 0; k < 4; k++) h[k] = __floats2half2_rn(acc[2*k], acc[2*k+1]);
    *reinterpret_cast<uint4*>(dst + (size_t)node * C + lane * 8) =
        *reinterpret_cast<uint4*>(h);
}

// ---------------- tensor-core GEMM ----------------
// out[M,256] = A[M,256](fp16) @ W[256,256]^T(fp16) + bias, fp32 accum.
// Block: 256 thr (8 warps), tile M=128 N=64, BK=64.
#define BK 64

__global__ void hgemm_kernel(const __half* __restrict__ A,
                             const float* __restrict__ bias,
                             float* __restrict__ out) {
    __shared__ __half As[128 * BK];  // swizzled: row*64 + (chunk^(row&7))*8
    __shared__ __half Bs[64 * BK];

    int tid = threadIdx.x;
    int lane = tid & 31;
    int warp = tid >> 5;
    int wm = warp & 3;
    int wn = warp >> 2;
    int g  = lane >> 2;
    int tg = lane & 3;

    int m0 = blockIdx.x * 128;
    int n0 = blockIdx.y * 64;

    float d[2][4][4] = {};

    for (int ks = 0; ks < C / BK; ks++) {
        int k0 = ks * BK;
        #pragma unroll
        for (int i = 0; i < 4; i++) {
            int lin = tid + i * 256;
            int row = lin >> 3;
            int ch  = lin & 7;
            int gm  = m0 + row;
            uint4 v = make_uint4(0, 0, 0, 0);
            if (gm < N_NODES)
                v = *reinterpret_cast<const uint4*>(A + (size_t)gm * C + k0 + ch * 8);
            *reinterpret_cast<uint4*>(&As[row * BK + ((ch ^ (row & 7)) * 8)]) = v;
        }
        #pragma unroll
        for (int i = 0; i < 2; i++) {
            int lin = tid + i * 256;
            int row = lin >> 3;
            int ch  = lin & 7;
            uint4 v = *reinterpret_cast<const uint4*>(g_hW + (size_t)(n0 + row) * C + k0 + ch * 8);
            *reinterpret_cast<uint4*>(&Bs[row * BK + ((ch ^ (row & 7)) * 8)]) = v;
        }
        __syncthreads();

        #pragma unroll
        for (int kc = 0; kc < BK / 16; kc++) {
            unsigned a[2][4];
            #pragma unroll
            for (int sm = 0; sm < 2; sm++) {
                int r0 = wm * 32 + sm * 16 + g;
                int r1 = r0 + 8;
                a[sm][0] = *reinterpret_cast<const unsigned*>(&As[r0 * BK + (((kc * 2)     ^ (r0 & 7)) * 8) + tg * 2]);
                a[sm][1] = *reinterpret_cast<const unsigned*>(&As[r1 * BK + (((kc * 2)     ^ (r1 & 7)) * 8) + tg * 2]);
                a[sm][2] = *reinterpret_cast<const unsigned*>(&As[r0 * BK + (((kc * 2 + 1) ^ (r0 & 7)) * 8) + tg * 2]);
                a[sm][3] = *reinterpret_cast<const unsigned*>(&As[r1 * BK + (((kc * 2 + 1) ^ (r1 & 7)) * 8) + tg * 2]);
            }
            #pragma unroll
            for (int sn = 0; sn < 4; sn++) {
                int nr = wn * 32 + sn * 8 + g;
                unsigned b0 = *reinterpret_cast<const unsigned*>(&Bs[nr * BK + (((kc * 2)     ^ (nr & 7)) * 8) + tg * 2]);
                unsigned b1 = *reinterpret_cast<const unsigned*>(&Bs[nr * BK + (((kc * 2 + 1) ^ (nr & 7)) * 8) + tg * 2]);
                #pragma unroll
                for (int sm = 0; sm < 2; sm++) {
                    asm volatile(
                        "mma.sync.aligned.m16n8k16.row.col.f32.f16.f16.f32 "
                        "{%0,%1,%2,%3}, {%4,%5,%6,%7}, {%8,%9}, {%0,%1,%2,%3};"
                        : "+f"(d[sm][sn][0]), "+f"(d[sm][sn][1]),
                          "+f"(d[sm][sn][2]), "+f"(d[sm][sn][3])
                        : "r"(a[sm][0]), "r"(a[sm][1]), "r"(a[sm][2]), "r"(a[sm][3]),
                          "r"(b0), "r"(b1));
                }
            }
        }
        __syncthreads();
    }

    #pragma unroll
    for (int sm = 0; sm < 2; sm++) {
        #pragma unroll
        for (int sn = 0; sn < 4; sn++) {
            int col = n0 + wn * 32 + sn * 8 + tg * 2;
            float b0 = bias[col], b1 = bias[col + 1];
            int r0 = m0 + wm * 32 + sm * 16 + g;
            if (r0 < N_NODES) {
                float2 v = make_float2(d[sm][sn][0] + b0, d[sm][sn][1] + b1);
                *reinterpret_cast<float2*>(out + (size_t)r0 * C + col) = v;
            }
            int r1 = r0 + 8;
            if (r1 < N_NODES) {
                float2 v = make_float2(d[sm][sn][2] + b0, d[sm][sn][3] + b1);
                *reinterpret_cast<float2*>(out + (size_t)r1 * C + col) = v;
            }
        }
    }
}

// ---------------- launch ----------------

extern "C" void kernel_launch(void* const* d_in, const int* in_sizes, int n_in,
                              void* d_out, int out_size) {
    const float* x  = (const float*)d_in[0];
    const void*  ei = d_in[1];
    const float* w  = (const float*)d_in[2];
    const float* lw = (const float*)d_in[3];
    const float* lb = (const float*)d_in[4];
    float* out = (float*)d_out;

    __half *hA, *hB;
    cudaGetSymbolAddress((void**)&hA, g_hA);
    cudaGetSymbolAddress((void**)&hB, g_hB);

    const int T = 256;

    // CSR build (4 launches)
    init_kernel<<<80, T>>>(ei);
    extract_kernel<<<(EDGES + T - 1) / T, T>>>(ei, w);
    scan_kernel<<<1, 1024>>>();
    fill_kernel<<<(EDGES + T - 1) / T, T>>>(w);

    // normalize + W conversion (1 launch)
    norm_convw_kernel<<<NB_NORM + 32, T>>>(x, lw);

    // hops: hA -> hB -> hA
    int ggrid = (N_NODES * 32 + T - 1) / T;
    gather_kernel<<<ggrid, T>>>(hA, hB);
    gather_kernel<<<ggrid, T>>>(hB, hA);

    // tensor-core linear
    dim3 lgrid((N_NODES + 127) / 128, C / 64);
    hgemm_kernel<<<lgrid, T>>>(hA, lb, out);
}

// round 7
// speedup vs baseline: 7.2451x; 1.0180x over previous
#include <cuda_runtime.h>
#include <cuda_fp16.h>

#define N_NODES 20000
#define EDGES   640000
#define C       256

// ---------------- scratch ----------------
__device__ __half g_hA[N_NODES * C];    // x_norm fp16, later hop2 output (GEMM A)
__device__ __half g_hB[N_NODES * C];    // hop1 output fp16
__device__ __half g_hW[C * C];          // fp16 weights [n][k]
__device__ float  g_deg[N_NODES];
__device__ int    g_cnt[N_NODES];
__device__ int    g_ptr[N_NODES + 1];
__device__ int    g_cursor[N_NODES];
__device__ __align__(16) int2   g_rc[EDGES];    // packed (row, col)
__device__ __align__(16) float2 g_edge[EDGES];  // packed (srcidx-as-bits, wval)
__device__ int    g_idx64;

// ---------------- setup kernels ----------------

// fused: zero deg/cnt (all blocks) + int64/int32 detection (block 0)
__global__ void init_kernel(const void* ei) {
    int i = blockIdx.x * blockDim.x + threadIdx.x;
    for (int s = gridDim.x * blockDim.x; i < N_NODES; i += s) {
        g_deg[i] = 0.0f;
        g_cnt[i] = 0;
    }
    if (blockIdx.x == 0) {
        __shared__ int bad;
        if (threadIdx.x == 0) bad = 0;
        __syncthreads();
        const long long* p = (const long long*)ei;
        for (int k = threadIdx.x; k < 2048; k += blockDim.x) {
            long long v = p[k];
            if (v < 0 || v >= N_NODES) bad = 1;
        }
        __syncthreads();
        if (threadIdx.x == 0) g_idx64 = bad ? 0 : 1;
    }
}

__global__ void extract_kernel(const void* ei, const float* __restrict__ w) {
    int e = blockIdx.x * blockDim.x + threadIdx.x;
    if (e >= EDGES) return;
    long long r, c;
    if (g_idx64) {
        r = ((const long long*)ei)[e];
        c = ((const long long*)ei)[EDGES + e];
    } else {
        r = ((const int*)ei)[e];
        c = ((const int*)ei)[EDGES + e];
    }
    if (r < 0 || r >= N_NODES) r = 0;
    if (c < 0 || c >= N_NODES) c = 0;
    g_rc[e] = make_int2((int)r, (int)c);
    atomicAdd(&g_deg[c], w[e]);
    atomicAdd(&g_cnt[c], 1);
}

// fused: deg -> deg^-1/2 transform, then exclusive int4 scan of g_cnt -> g_ptr/g_cursor
__global__ void scan_kernel() {
    __shared__ int wsum[32];
    __shared__ int s_running;
    int tid = threadIdx.x;
    int lane = tid & 31, wid = tid >> 5;

    for (int i = tid; i < N_NODES; i += 1024) {
        float d = g_deg[i];
        g_deg[i] = (d > 0.0f) ? rsqrtf(d) : 0.0f;
    }
    if (tid == 0) s_running = 0;
    __syncthreads();

    const int NV = N_NODES / 4;   // 5000
    for (int base = 0; base < NV; base += 1024) {
        int iv = base + tid;
        int4 v = make_int4(0, 0, 0, 0);
        if (iv < NV) v = reinterpret_cast<const int4*>(g_cnt)[iv];
        int lsum = v.x + v.y + v.z + v.w;
        int s = lsum;
        #pragma unroll
        for (int o = 1; o < 32; o <<= 1) {
            int t = __shfl_up_sync(0xffffffffu, s, o);
            if (lane >= o) s += t;
        }
        if (lane == 31) wsum[wid] = s;
        __syncthreads();
        if (wid == 0) {
            int ws = wsum[lane];
            #pragma unroll
            for (int o = 1; o < 32; o <<= 1) {
                int t = __shfl_up_sync(0xffffffffu, ws, o);
                if (lane >= o) ws += t;
            }
            wsum[lane] = ws;
        }
        __syncthreads();
        int excl = s_running + s - lsum + (wid > 0 ? wsum[wid - 1] : 0);
        if (iv < NV) {
            int4 p;
            p.x = excl;
            p.y = p.x + v.x;
            p.z = p.y + v.y;
            p.w = p.z + v.z;
            reinterpret_cast<int4*>(g_ptr)[iv]    = p;
            reinterpret_cast<int4*>(g_cursor)[iv] = p;
        }
        __syncthreads();
        if (tid == 0) s_running += wsum[31];
        __syncthreads();
    }
    if (tid == 0) g_ptr[N_NODES] = s_running;
}

// fused 3-phase kernel:
//   blocks [0, NB_FILL)             : CSR fill (packed 8B records)
//   blocks [NB_FILL, NB_FILL+2500)  : L2-normalize x -> g_hA (warp/row)
//   blocks [NB_FILL+2500, +32)      : W -> fp16
#define NB_FILL 2500
__global__ void fill_norm_kernel(const float* __restrict__ w,
                                 const float* __restrict__ x,
                                 const float* __restrict__ W) {
    int b = blockIdx.x;
    if (b < NB_FILL) {
        int e = b * 256 + threadIdx.x;
        if (e >= EDGES) return;
        int2 rc = g_rc[e];
        int pos = atomicAdd(&g_cursor[rc.y], 1);
        float wval = g_deg[rc.x] * w[e] * g_deg[rc.y];
        g_edge[pos] = make_float2(__int_as_float(rc.x), wval);
        return;
    }
    b -= NB_FILL;
    if (b >= 2500) {
        int i = ((b - 2500) * 256 + threadIdx.x) * 8;
        if (i < C * C) {
            __half2 h[4];
            #pragma unroll
            for (int k = 0; k < 4; k++)
                h[k] = __floats2half2_rn(W[i + 2*k], W[i + 2*k + 1]);
            *reinterpret_cast<uint4*>(g_hW + i) = *reinterpret_cast<uint4*>(h);
        }
        return;
    }
    int warp = (b * 256 + threadIdx.x) >> 5;
    int lane = threadIdx.x & 31;
    if (warp >= N_NODES) return;
    const float4* xr = reinterpret_cast<const float4*>(x + (size_t)warp * C);
    float4 v0 = xr[lane * 2];
    float4 v1 = xr[lane * 2 + 1];
    float ss = v0.x*v0.x + v0.y*v0.y + v0.z*v0.z + v0.w*v0.w
             + v1.x*v1.x + v1.y*v1.y + v1.z*v1.z + v1.w*v1.w;
    #pragma unroll
    for (int o = 16; o; o >>= 1) ss += __shfl_xor_sync(0xffffffffu, ss, o);
    float inv = 1.0f / fmaxf(sqrtf(ss), 1e-12f);
    __half2 h[4];
    h[0] = __floats2half2_rn(v0.x * inv, v0.y * inv);
    h[1] = __floats2half2_rn(v0.z * inv, v0.w * inv);
    h[2] = __floats2half2_rn(v1.x * inv, v1.y * inv);
    h[3] = __floats2half2_rn(v1.z * inv, v1.w * inv);
    *reinterpret_cast<uint4*>(g_hA + (size_t)warp * C + lane * 8) =
        *reinterpret_cast<uint4*>(h);
}

// warp per target node: fp16 src rows, fp32 accumulate, fp16 out.
// 8-edge unroll with vectorized metadata loads (4x uint4 = 8 packed records).
__global__ void gather_kernel(const __half* __restrict__ src, __half* __restrict__ dst) {
    int node = (blockIdx.x * blockDim.x + threadIdx.x) >> 5;
    int lane = threadIdx.x & 31;
    if (node >= N_NODES) return;
    int i   = g_ptr[node];
    int end = g_ptr[node + 1];
    float acc[8] = {};

    // parity prologue so uint4 metadata loads are 16B-aligned
    if ((i & 1) && i < end) {
        float2 me = g_edge[i];
        int r = __float_as_int(me.x);
        float wv = me.y;
        uint4 v = *reinterpret_cast<const uint4*>(src + (size_t)r * C + lane * 8);
        const __half2* h = reinterpret_cast<const __half2*>(&v);
        #pragma unroll
        for (int k = 0; k < 4; k++) {
            float2 f = __half22float2(h[k]);
            acc[2*k]   += wv * f.x;
            acc[2*k+1] += wv * f.y;
        }
        i++;
    }

    for (; i + 8 <= end; i += 8) {
        uint4 m[4];
        #pragma unroll
        for (int j = 0; j < 4; j++)
            m[j] = *reinterpret_cast<const uint4*>(&g_edge[i + 2 * j]);
        int r[8]; float wv[8];
        #pragma unroll
        for (int j = 0; j < 4; j++) {
            r[2*j]   = (int)m[j].x;  wv[2*j]   = __uint_as_float(m[j].y);
            r[2*j+1] = (int)m[j].z;  wv[2*j+1] = __uint_as_float(m[j].w);
        }
        uint4 v[8];
        #pragma unroll
        for (int u = 0; u < 8; u++)
            v[u] = *reinterpret_cast<const uint4*>(src + (size_t)r[u] * C + lane * 8);
        #pragma unroll
        for (int u = 0; u < 8; u++) {
            const __half2* h = reinterpret_cast<const __half2*>(&v[u]);
            #pragma unroll
            for (int k = 0; k < 4; k++) {
                float2 f = __half22float2(h[k]);
                acc[2*k]   += wv[u] * f.x;
                acc[2*k+1] += wv[u] * f.y;
            }
        }
    }
    for (; i < end; i++) {
        float2 me = g_edge[i];
        int r = __float_as_int(me.x);
        float wv = me.y;
        uint4 v = *reinterpret_cast<const uint4*>(src + (size_t)r * C + lane * 8);
        const __half2* h = reinterpret_cast<const __half2*>(&v);
        #pragma unroll
        for (int k = 0; k < 4; k++) {
            float2 f = __half22float2(h[k]);
            acc[2*k]   += wv * f.x;
            acc[2*k+1] += wv * f.y;
        }
    }

    __half2 h[4];
    #pragma unroll
    for (int k = 0; k < 4; k++) h[k] = __floats2half2_rn(acc[2*k], acc[2*k+1]);
    *reinterpret_cast<uint4*>(dst + (size_t)node * C + lane * 8) =
        *reinterpret_cast<uint4*>(h);
}

// ---------------- tensor-core GEMM ----------------
#define BK 64

__global__ void hgemm_kernel(const __half* __restrict__ A,
                             const float* __restrict__ bias,
                             float* __restrict__ out) {
    __shared__ __half As[128 * BK];  // swizzled: row*64 + (chunk^(row&7))*8
    __shared__ __half Bs[64 * BK];

    int tid = threadIdx.x;
    int lane = tid & 31;
    int warp = tid >> 5;
    int wm = warp & 3;
    int wn = warp >> 2;
    int g  = lane >> 2;
    int tg = lane & 3;

    int m0 = blockIdx.x * 128;
    int n0 = blockIdx.y * 64;

    float d[2][4][4] = {};

    for (int ks = 0; ks < C / BK; ks++) {
        int k0 = ks * BK;
        #pragma unroll
        for (int i = 0; i < 4; i++) {
            int lin = tid + i * 256;
            int row = lin >> 3;
            int ch  = lin & 7;
            int gm  = m0 + row;
            uint4 v = make_uint4(0, 0, 0, 0);
            if (gm < N_NODES)
                v = *reinterpret_cast<const uint4*>(A + (size_t)gm * C + k0 + ch * 8);
            *reinterpret_cast<uint4*>(&As[row * BK + ((ch ^ (row & 7)) * 8)]) = v;
        }
        #pragma unroll
        for (int i = 0; i < 2; i++) {
            int lin = tid + i * 256;
            int row = lin >> 3;
            int ch  = lin & 7;
            uint4 v = *reinterpret_cast<const uint4*>(g_hW + (size_t)(n0 + row) * C + k0 + ch * 8);
            *reinterpret_cast<uint4*>(&Bs[row * BK + ((ch ^ (row & 7)) * 8)]) = v;
        }
        __syncthreads();

        #pragma unroll
        for (int kc = 0; kc < BK / 16; kc++) {
            unsigned a[2][4];
            #pragma unroll
            for (int sm = 0; sm < 2; sm++) {
                int r0 = wm * 32 + sm * 16 + g;
                int r1 = r0 + 8;
                a[sm][0] = *reinterpret_cast<const unsigned*>(&As[r0 * BK + (((kc * 2)     ^ (r0 & 7)) * 8) + tg * 2]);
                a[sm][1] = *reinterpret_cast<const unsigned*>(&As[r1 * BK + (((kc * 2)     ^ (r1 & 7)) * 8) + tg * 2]);
                a[sm][2] = *reinterpret_cast<const unsigned*>(&As[r0 * BK + (((kc * 2 + 1) ^ (r0 & 7)) * 8) + tg * 2]);
                a[sm][3] = *reinterpret_cast<const unsigned*>(&As[r1 * BK + (((kc * 2 + 1) ^ (r1 & 7)) * 8) + tg * 2]);
            }
            #pragma unroll
            for (int sn = 0; sn < 4; sn++) {
                int nr = wn * 32 + sn * 8 + g;
                unsigned b0 = *reinterpret_cast<const unsigned*>(&Bs[nr * BK + (((kc * 2)     ^ (nr & 7)) * 8) + tg * 2]);
                unsigned b1 = *reinterpret_cast<const unsigned*>(&Bs[nr * BK + (((kc * 2 + 1) ^ (nr & 7)) * 8) + tg * 2]);
                #pragma unroll
                for (int sm = 0; sm < 2; sm++) {
                    asm volatile(
                        "mma.sync.aligned.m16n8k16.row.col.f32.f16.f16.f32 "
                        "{%0,%1,%2,%3}, {%4,%5,%6,%7}, {%8,%9}, {%0,%1,%2,%3};"
                        : "+f"(d[sm][sn][0]), "+f"(d[sm][sn][1]),
                          "+f"(d[sm][sn][2]), "+f"(d[sm][sn][3])
                        : "r"(a[sm][0]), "r"(a[sm][1]), "r"(a[sm][2]), "r"(a[sm][3]),
                          "r"(b0), "r"(b1));
                }
            }
        }
        __syncthreads();
    }

    #pragma unroll
    for (int sm = 0; sm < 2; sm++) {
        #pragma unroll
        for (int sn = 0; sn < 4; sn++) {
            int col = n0 + wn * 32 + sn * 8 + tg * 2;
            float b0 = bias[col], b1 = bias[col + 1];
            int r0 = m0 + wm * 32 + sm * 16 + g;
            if (r0 < N_NODES) {
                float2 v = make_float2(d[sm][sn][0] + b0, d[sm][sn][1] + b1);
                *reinterpret_cast<float2*>(out + (size_t)r0 * C + col) = v;
            }
            int r1 = r0 + 8;
            if (r1 < N_NODES) {
                float2 v = make_float2(d[sm][sn][2] + b0, d[sm][sn][3] + b1);
                *reinterpret_cast<float2*>(out + (size_t)r1 * C + col) = v;
            }
        }
    }
}

// ---------------- launch ----------------

extern "C" void kernel_launch(void* const* d_in, const int* in_sizes, int n_in,
                              void* d_out, int out_size) {
    const float* x  = (const float*)d_in[0];
    const void*  ei = d_in[1];
    const float* w  = (const float*)d_in[2];
    const float* lw = (const float*)d_in[3];
    const float* lb = (const float*)d_in[4];
    float* out = (float*)d_out;

    __half *hA, *hB;
    cudaGetSymbolAddress((void**)&hA, g_hA);
    cudaGetSymbolAddress((void**)&hB, g_hB);

    const int T = 256;

    // CSR build + feature prep (4 launches)
    init_kernel<<<80, T>>>(ei);
    extract_kernel<<<(EDGES + T - 1) / T, T>>>(ei, w);
    scan_kernel<<<1, 1024>>>();
    fill_norm_kernel<<<NB_FILL + 2500 + 32, T>>>(w, x, lw);

    // hops: hA -> hB -> hA
    int ggrid = (N_NODES * 32 + T - 1) / T;
    gather_kernel<<<ggrid, T>>>(hA, hB);
    gather_kernel<<<ggrid, T>>>(hB, hA);

    // tensor-core linear
    dim3 lgrid((N_NODES + 127) / 128, C / 64);
    hgemm_kernel<<<lgrid, T>>>(hA, lb, out);
}

// round 8
// speedup vs baseline: 7.9677x; 1.0997x over previous
#include <cuda_runtime.h>
#include <cuda_fp16.h>

#define N_NODES 20000
#define EDGES   640000
#define C       256

// ---------------- scratch ----------------
__device__ __half g_hA[N_NODES * C];    // x_norm fp16, later hop2 output (GEMM A)
__device__ __half g_hB[N_NODES * C];    // hop1 output fp16
__device__ __half g_hW[C * C];          // fp16 weights [n][k]
__device__ unsigned long long g_pk[N_NODES];  // (cnt<<32) | deg_fix20  -- self-cleaned
__device__ float  g_deg[N_NODES];       // deg^-1/2
__device__ int    g_ptr[N_NODES + 1];
__device__ int    g_cursor[N_NODES];
__device__ __align__(16) int2   g_rc[EDGES];    // packed (row, col)
__device__ __align__(16) float2 g_edge[EDGES];  // packed (srcidx-as-bits, wval)

// ---------------- setup kernels ----------------

// extract: per-block dtype detection + packed-index materialization +
// single packed 64-bit atomic for (count, fixed-point weighted degree).
__global__ void extract_kernel(const void* ei, const float* __restrict__ w) {
    __shared__ int s_bad;
    if (threadIdx.x == 0) s_bad = 0;
    __syncthreads();
    {
        const long long* p = (const long long*)ei;
        if (threadIdx.x < 128) {
            long long v = p[threadIdx.x];
            if (v < 0 || v >= N_NODES) s_bad = 1;
        }
    }
    __syncthreads();
    int is64 = !s_bad;

    int e = blockIdx.x * 256 + threadIdx.x;
    if (e >= EDGES) return;
    long long r, c;
    if (is64) {
        r = ((const long long*)ei)[e];
        c = ((const long long*)ei)[EDGES + e];
    } else {
        r = ((const int*)ei)[e];
        c = ((const int*)ei)[EDGES + e];
    }
    if (r < 0 || r >= N_NODES) r = 0;
    if (c < 0 || c >= N_NODES) c = 0;
    g_rc[e] = make_int2((int)r, (int)c);
    unsigned wfix = (unsigned)(w[e] * 1048576.0f + 0.5f);
    atomicAdd(&g_pk[c], (1ULL << 32) | (unsigned long long)wfix);
}

// scan: unpack g_pk -> dis + counts, self-clean g_pk, exclusive scan -> ptr/cursor.
__global__ void scan_kernel() {
    __shared__ int wsum[32];
    __shared__ int s_running;
    int tid = threadIdx.x;                 // 1024 threads
    int lane = tid & 31, wid = tid >> 5;
    if (tid == 0) s_running = 0;
    __syncthreads();

    const int NV = N_NODES / 4;            // 5000 groups of 4 nodes
    for (int base = 0; base < NV; base += 1024) {
        int iv = base + tid;
        int c4[4] = {0, 0, 0, 0};
        if (iv < NV) {
            ulonglong2 p0 = reinterpret_cast<const ulonglong2*>(g_pk)[iv * 2];
            ulonglong2 p1 = reinterpret_cast<const ulonglong2*>(g_pk)[iv * 2 + 1];
            // self-clean for next call
            reinterpret_cast<ulonglong2*>(g_pk)[iv * 2]     = make_ulonglong2(0ULL, 0ULL);
            reinterpret_cast<ulonglong2*>(g_pk)[iv * 2 + 1] = make_ulonglong2(0ULL, 0ULL);
            c4[0] = (int)(p0.x >> 32); c4[1] = (int)(p0.y >> 32);
            c4[2] = (int)(p1.x >> 32); c4[3] = (int)(p1.y >> 32);
            const float S = 1.0f / 1048576.0f;
            float d0 = (float)(unsigned)(p0.x & 0xffffffffULL) * S;
            float d1 = (float)(unsigned)(p0.y & 0xffffffffULL) * S;
            float d2 = (float)(unsigned)(p1.x & 0xffffffffULL) * S;
            float d3 = (float)(unsigned)(p1.y & 0xffffffffULL) * S;
            float4 dis;
            dis.x = (d0 > 0.0f) ? rsqrtf(d0) : 0.0f;
            dis.y = (d1 > 0.0f) ? rsqrtf(d1) : 0.0f;
            dis.z = (d2 > 0.0f) ? rsqrtf(d2) : 0.0f;
            dis.w = (d3 > 0.0f) ? rsqrtf(d3) : 0.0f;
            reinterpret_cast<float4*>(g_deg)[iv] = dis;
        }
        int lsum = c4[0] + c4[1] + c4[2] + c4[3];
        int s = lsum;
        #pragma unroll
        for (int o = 1; o < 32; o <<= 1) {
            int t = __shfl_up_sync(0xffffffffu, s, o);
            if (lane >= o) s += t;
        }
        if (lane == 31) wsum[wid] = s;
        __syncthreads();
        if (wid == 0) {
            int ws = wsum[lane];
            #pragma unroll
            for (int o = 1; o < 32; o <<= 1) {
                int t = __shfl_up_sync(0xffffffffu, ws, o);
                if (lane >= o) ws += t;
            }
            wsum[lane] = ws;
        }
        __syncthreads();
        int excl = s_running + s - lsum + (wid > 0 ? wsum[wid - 1] : 0);
        if (iv < NV) {
            int4 p;
            p.x = excl;
            p.y = p.x + c4[0];
            p.z = p.y + c4[1];
            p.w = p.z + c4[2];
            reinterpret_cast<int4*>(g_ptr)[iv]    = p;
            reinterpret_cast<int4*>(g_cursor)[iv] = p;
        }
        __syncthreads();
        if (tid == 0) s_running += wsum[31];
        __syncthreads();
    }
    if (tid == 0) g_ptr[N_NODES] = s_running;
}

// fused 3-phase kernel:
//   blocks [0, NB_FILL)             : CSR fill (packed 8B records)
//   blocks [NB_FILL, NB_FILL+2500)  : L2-normalize x -> g_hA (warp/row)
//   blocks [NB_FILL+2500, +32)      : W -> fp16
#define NB_FILL 2500
__global__ void fill_norm_kernel(const float* __restrict__ w,
                                 const float* __restrict__ x,
                                 const float* __restrict__ W) {
    int b = blockIdx.x;
    if (b < NB_FILL) {
        int e = b * 256 + threadIdx.x;
        if (e >= EDGES) return;
        int2 rc = g_rc[e];
        int pos = atomicAdd(&g_cursor[rc.y], 1);
        float wval = g_deg[rc.x] * w[e] * g_deg[rc.y];
        g_edge[pos] = make_float2(__int_as_float(rc.x), wval);
        return;
    }
    b -= NB_FILL;
    if (b >= 2500) {
        int i = ((b - 2500) * 256 + threadIdx.x) * 8;
        if (i < C * C) {
            __half2 h[4];
            #pragma unroll
            for (int k = 0; k < 4; k++)
                h[k] = __floats2half2_rn(W[i + 2*k], W[i + 2*k + 1]);
            *reinterpret_cast<uint4*>(g_hW + i) = *reinterpret_cast<uint4*>(h);
        }
        return;
    }
    int warp = (b * 256 + threadIdx.x) >> 5;
    int lane = threadIdx.x & 31;
    if (warp >= N_NODES) return;
    const float4* xr = reinterpret_cast<const float4*>(x + (size_t)warp * C);
    float4 v0 = xr[lane * 2];
    float4 v1 = xr[lane * 2 + 1];
    float ss = v0.x*v0.x + v0.y*v0.y + v0.z*v0.z + v0.w*v0.w
             + v1.x*v1.x + v1.y*v1.y + v1.z*v1.z + v1.w*v1.w;
    #pragma unroll
    for (int o = 16; o; o >>= 1) ss += __shfl_xor_sync(0xffffffffu, ss, o);
    float inv = 1.0f / fmaxf(sqrtf(ss), 1e-12f);
    __half2 h[4];
    h[0] = __floats2half2_rn(v0.x * inv, v0.y * inv);
    h[1] = __floats2half2_rn(v0.z * inv, v0.w * inv);
    h[2] = __floats2half2_rn(v1.x * inv, v1.y * inv);
    h[3] = __floats2half2_rn(v1.z * inv, v1.w * inv);
    *reinterpret_cast<uint4*>(g_hA + (size_t)warp * C + lane * 8) =
        *reinterpret_cast<uint4*>(h);
}

// warp per target node: fp16 src rows, fp32 accumulate, fp16 out.
__global__ void gather_kernel(const __half* __restrict__ src, __half* __restrict__ dst) {
    int node = (blockIdx.x * blockDim.x + threadIdx.x) >> 5;
    int lane = threadIdx.x & 31;
    if (node >= N_NODES) return;
    int i   = g_ptr[node];
    int end = g_ptr[node + 1];
    float acc[8] = {};

    if ((i & 1) && i < end) {
        float2 me = g_edge[i];
        int r = __float_as_int(me.x);
        float wv = me.y;
        uint4 v = *reinterpret_cast<const uint4*>(src + (size_t)r * C + lane * 8);
        const __half2* h = reinterpret_cast<const __half2*>(&v);
        #pragma unroll
        for (int k = 0; k < 4; k++) {
            float2 f = __half22float2(h[k]);
            acc[2*k]   += wv * f.x;
            acc[2*k+1] += wv * f.y;
        }
        i++;
    }

    for (; i + 8 <= end; i += 8) {
        uint4 m[4];
        #pragma unroll
        for (int j = 0; j < 4; j++)
            m[j] = *reinterpret_cast<const uint4*>(&g_edge[i + 2 * j]);
        int r[8]; float wv[8];
        #pragma unroll
        for (int j = 0; j < 4; j++) {
            r[2*j]   = (int)m[j].x;  wv[2*j]   = __uint_as_float(m[j].y);
            r[2*j+1] = (int)m[j].z;  wv[2*j+1] = __uint_as_float(m[j].w);
        }
        uint4 v[8];
        #pragma unroll
        for (int u = 0; u < 8; u++)
            v[u] = *reinterpret_cast<const uint4*>(src + (size_t)r[u] * C + lane * 8);
        #pragma unroll
        for (int u = 0; u < 8; u++) {
            const __half2* h = reinterpret_cast<const __half2*>(&v[u]);
            #pragma unroll
            for (int k = 0; k < 4; k++) {
                float2 f = __half22float2(h[k]);
                acc[2*k]   += wv[u] * f.x;
                acc[2*k+1] += wv[u] * f.y;
            }
        }
    }
    for (; i < end; i++) {
        float2 me = g_edge[i];
        int r = __float_as_int(me.x);
        float wv = me.y;
        uint4 v = *reinterpret_cast<const uint4*>(src + (size_t)r * C + lane * 8);
        const __half2* h = reinterpret_cast<const __half2*>(&v);
        #pragma unroll
        for (int k = 0; k < 4; k++) {
            float2 f = __half22float2(h[k]);
            acc[2*k]   += wv * f.x;
            acc[2*k+1] += wv * f.y;
        }
    }

    __half2 h[4];
    #pragma unroll
    for (int k = 0; k < 4; k++) h[k] = __floats2half2_rn(acc[2*k], acc[2*k+1]);
    *reinterpret_cast<uint4*>(dst + (size_t)node * C + lane * 8) =
        *reinterpret_cast<uint4*>(h);
}

// ---------------- tensor-core GEMM (register double-buffered) ----------------
#define BK 64

__global__ void hgemm_kernel(const __half* __restrict__ A,
                             const float* __restrict__ bias,
                             float* __restrict__ out) {
    __shared__ __half As[128 * BK];
    __shared__ __half Bs[64 * BK];

    int tid = threadIdx.x;
    int lane = tid & 31;
    int warp = tid >> 5;
    int wm = warp & 3;
    int wn = warp >> 2;
    int g  = lane >> 2;
    int tg = lane & 3;

    int m0 = blockIdx.x * 128;
    int n0 = blockIdx.y * 64;

    float d[2][4][4] = {};
    uint4 pa[4], pb[2];

    // prefetch first K-chunk into registers
    #pragma unroll
    for (int i = 0; i < 4; i++) {
        int lin = tid + i * 256;
        int row = lin >> 3;
        int ch  = lin & 7;
        int gm  = m0 + row;
        pa[i] = make_uint4(0, 0, 0, 0);
        if (gm < N_NODES)
            pa[i] = *reinterpret_cast<const uint4*>(A + (size_t)gm * C + ch * 8);
    }
    #pragma unroll
    for (int i = 0; i < 2; i++) {
        int lin = tid + i * 256;
        int row = lin >> 3;
        int ch  = lin & 7;
        pb[i] = *reinterpret_cast<const uint4*>(g_hW + (size_t)(n0 + row) * C + ch * 8);
    }

    #pragma unroll
    for (int ks = 0; ks < C / BK; ks++) {
        // regs -> smem
        #pragma unroll
        for (int i = 0; i < 4; i++) {
            int lin = tid + i * 256;
            int row = lin >> 3;
            int ch  = lin & 7;
            *reinterpret_cast<uint4*>(&As[row * BK + ((ch ^ (row & 7)) * 8)]) = pa[i];
        }
        #pragma unroll
        for (int i = 0; i < 2; i++) {
            int lin = tid + i * 256;
            int row = lin >> 3;
            int ch  = lin & 7;
            *reinterpret_cast<uint4*>(&Bs[row * BK + ((ch ^ (row & 7)) * 8)]) = pb[i];
        }
        __syncthreads();

        // prefetch next K-chunk during MMA
        if (ks + 1 < C / BK) {
            int k0 = (ks + 1) * BK;
            #pragma unroll
            for (int i = 0; i < 4; i++) {
                int lin = tid + i * 256;
                int row = lin >> 3;
                int ch  = lin & 7;
                int gm  = m0 + row;
                pa[i] = make_uint4(0, 0, 0, 0);
                if (gm < N_NODES)
                    pa[i] = *reinterpret_cast<const uint4*>(A + (size_t)gm * C + k0 + ch * 8);
            }
            #pragma unroll
            for (int i = 0; i < 2; i++) {
                int lin = tid + i * 256;
                int row = lin >> 3;
                int ch  = lin & 7;
                pb[i] = *reinterpret_cast<const uint4*>(g_hW + (size_t)(n0 + row) * C + k0 + ch * 8);
            }
        }

        #pragma unroll
        for (int kc = 0; kc < BK / 16; kc++) {
            unsigned a[2][4];
            #pragma unroll
            for (int sm = 0; sm < 2; sm++) {
                int r0 = wm * 32 + sm * 16 + g;
                int r1 = r0 + 8;
                a[sm][0] = *reinterpret_cast<const unsigned*>(&As[r0 * BK + (((kc * 2)     ^ (r0 & 7)) * 8) + tg * 2]);
                a[sm][1] = *reinterpret_cast<const unsigned*>(&As[r1 * BK + (((kc * 2)     ^ (r1 & 7)) * 8) + tg * 2]);
                a[sm][2] = *reinterpret_cast<const unsigned*>(&As[r0 * BK + (((kc * 2 + 1) ^ (r0 & 7)) * 8) + tg * 2]);
                a[sm][3] = *reinterpret_cast<const unsigned*>(&As[r1 * BK + (((kc * 2 + 1) ^ (r1 & 7)) * 8) + tg * 2]);
            }
            #pragma unroll
            for (int sn = 0; sn < 4; sn++) {
                int nr = wn * 32 + sn * 8 + g;
                unsigned b0 = *reinterpret_cast<const unsigned*>(&Bs[nr * BK + (((kc * 2)     ^ (nr & 7)) * 8) + tg * 2]);
                unsigned b1 = *reinterpret_cast<const unsigned*>(&Bs[nr * BK + (((kc * 2 + 1) ^ (nr & 7)) * 8) + tg * 2]);
                #pragma unroll
                for (int sm = 0; sm < 2; sm++) {
                    asm volatile(
                        "mma.sync.aligned.m16n8k16.row.col.f32.f16.f16.f32 "
                        "{%0,%1,%2,%3}, {%4,%5,%6,%7}, {%8,%9}, {%0,%1,%2,%3};"
                        : "+f"(d[sm][sn][0]), "+f"(d[sm][sn][1]),
                          "+f"(d[sm][sn][2]), "+f"(d[sm][sn][3])
                        : "r"(a[sm][0]), "r"(a[sm][1]), "r"(a[sm][2]), "r"(a[sm][3]),
                          "r"(b0), "r"(b1));
                }
            }
        }
        __syncthreads();
    }

    #pragma unroll
    for (int sm = 0; sm < 2; sm++) {
        #pragma unroll
        for (int sn = 0; sn < 4; sn++) {
            int col = n0 + wn * 32 + sn * 8 + tg * 2;
            float b0 = bias[col], b1 = bias[col + 1];
            int r0 = m0 + wm * 32 + sm * 16 + g;
            if (r0 < N_NODES) {
                float2 v = make_float2(d[sm][sn][0] + b0, d[sm][sn][1] + b1);
                *reinterpret_cast<float2*>(out + (size_t)r0 * C + col) = v;
            }
            int r1 = r0 + 8;
            if (r1 < N_NODES) {
                float2 v = make_float2(d[sm][sn][2] + b0, d[sm][sn][3] + b1);
                *reinterpret_cast<float2*>(out + (size_t)r1 * C + col) = v;
            }
        }
    }
}

// ---------------- launch ----------------

extern "C" void kernel_launch(void* const* d_in, const int* in_sizes, int n_in,
                              void* d_out, int out_size) {
    const float* x  = (const float*)d_in[0];
    const void*  ei = d_in[1];
    const float* w  = (const float*)d_in[2];
    const float* lw = (const float*)d_in[3];
    const float* lb = (const float*)d_in[4];
    float* out = (float*)d_out;

    __half *hA, *hB;
    cudaGetSymbolAddress((void**)&hA, g_hA);
    cudaGetSymbolAddress((void**)&hB, g_hB);

    const int T = 256;

    // CSR build + feature prep (3 launches)
    extract_kernel<<<(EDGES + T - 1) / T, T>>>(ei, w);
    scan_kernel<<<1, 1024>>>();
    fill_norm_kernel<<<NB_FILL + 2500 + 32, T>>>(w, x, lw);

    // hops: hA -> hB -> hA
    int ggrid = (N_NODES * 32 + T - 1) / T;
    gather_kernel<<<ggrid, T>>>(hA, hB);
    gather_kernel<<<ggrid, T>>>(hB, hA);

    // tensor-core linear
    dim3 lgrid((N_NODES + 127) / 128, C / 64);
    hgemm_kernel<<<lgrid, T>>>(hA, lb, out);
}